// round 1
// baseline (speedup 1.0000x reference)
#include <cuda_runtime.h>
#include <cuda_bf16.h>
#include <cstdint>

// Problem constants
#define Bx 2
#define Tx 2048
#define Cx 1024
#define Hx 16
#define Dx 64
#define Mrows (Bx*Tx)   // 4096

// Scratch in __device__ globals (no allocations allowed)
__device__ float g_q[(size_t)Bx*Hx*Tx*Dx];   // [B,H,T,D]
__device__ float g_k[(size_t)Bx*Hx*Tx*Dx];
__device__ float g_v[(size_t)Bx*Hx*Tx*Dx];
__device__ float g_y[(size_t)Mrows*Cx];      // [B*T, C]

// ---------------------------------------------------------------------------
// SGEMM: out[M=4096, N=1024] = X[4096,1024] @ W[1024,1024]^T + bias
// W is row-major [out_features, in_features] (torch Linear convention).
// split==1: write into [B,H,T,D] layout; split==0: flat [M,N].
// ---------------------------------------------------------------------------
__global__ __launch_bounds__(256) void sgemm_kernel(
    const float* __restrict__ X, const float* __restrict__ W,
    const float* __restrict__ bias, float* __restrict__ out, int split)
{
    constexpr int BM = 128, BN = 128, BK = 16;
    constexpr int Kdim = 1024;
    __shared__ float Xs[BK][BM + 4];
    __shared__ float Ws[BK][BN + 4];

    const int tid = threadIdx.x;
    const int bm = blockIdx.y * BM;
    const int bn = blockIdx.x * BN;
    const int tx = tid & 15;   // n dim
    const int ty = tid >> 4;   // m dim

    float acc[8][8];
#pragma unroll
    for (int i = 0; i < 8; i++)
#pragma unroll
        for (int j = 0; j < 8; j++) acc[i][j] = 0.0f;

    for (int k0 = 0; k0 < Kdim; k0 += BK) {
        // Load tiles: 128 rows x 16 cols each (512 float4s), 2 per thread
#pragma unroll
        for (int l = 0; l < 2; l++) {
            int f  = tid + l * 256;        // 0..511
            int r  = f >> 2;               // row 0..127
            int c4 = (f & 3) * 4;          // col within BK
            float4 xv = *(const float4*)&X[(size_t)(bm + r) * Kdim + k0 + c4];
            Xs[c4 + 0][r] = xv.x; Xs[c4 + 1][r] = xv.y;
            Xs[c4 + 2][r] = xv.z; Xs[c4 + 3][r] = xv.w;
            float4 wv = *(const float4*)&W[(size_t)(bn + r) * Kdim + k0 + c4];
            Ws[c4 + 0][r] = wv.x; Ws[c4 + 1][r] = wv.y;
            Ws[c4 + 2][r] = wv.z; Ws[c4 + 3][r] = wv.w;
        }
        __syncthreads();

#pragma unroll
        for (int kk = 0; kk < BK; kk++) {
            float a[8], b[8];
            *(float4*)&a[0] = *(const float4*)&Xs[kk][ty * 8];
            *(float4*)&a[4] = *(const float4*)&Xs[kk][ty * 8 + 4];
            *(float4*)&b[0] = *(const float4*)&Ws[kk][tx * 8];
            *(float4*)&b[4] = *(const float4*)&Ws[kk][tx * 8 + 4];
#pragma unroll
            for (int i = 0; i < 8; i++)
#pragma unroll
                for (int j = 0; j < 8; j++)
                    acc[i][j] = fmaf(a[i], b[j], acc[i][j]);
        }
        __syncthreads();
    }

    // Epilogue
#pragma unroll
    for (int i = 0; i < 8; i++) {
        int row = bm + ty * 8 + i;
#pragma unroll
        for (int j = 0; j < 8; j++) {
            int col = bn + tx * 8 + j;
            float v = acc[i][j] + bias[col];
            if (split) {
                int b_ = row >> 11;        // row / T
                int t_ = row & 2047;
                int h_ = col >> 6;         // col / D
                int d_ = col & 63;
                out[(((size_t)(b_ * Hx + h_) * Tx) + t_) * Dx + d_] = v;
            } else {
                out[(size_t)row * Cx + col] = v;
            }
        }
    }
}

// ---------------------------------------------------------------------------
// Flash-attention style causal attention.
// q,k,v: [B,H,T,D] fp32.  y: [B,T,C] fp32.
// Block: 64 query rows x full D=64. Iterates 64-key tiles up to causal limit.
// 256 threads as 16x16, each owns a 4x4 microtile.
// ---------------------------------------------------------------------------
__global__ __launch_bounds__(256) void attn_kernel(
    const float* __restrict__ q, const float* __restrict__ k,
    const float* __restrict__ v, float* __restrict__ y)
{
    constexpr int AM = 64, AN = 64, DP = 68, NP = 68;
    extern __shared__ float sm[];
    float* Qs = sm;                  // AM * DP
    float* Ks = Qs + AM * DP;        // AN * DP
    float* Vs = Ks + AN * DP;        // AN * DP
    float* Ps = Vs + AN * DP;        // AM * NP

    const int bh = blockIdx.y;          // b*H + h
    const int q0 = blockIdx.x * AM;
    const int tid = threadIdx.x;
    const int tx = tid & 15;
    const int ty = tid >> 4;
    const float* qb = q + (size_t)bh * Tx * Dx;
    const float* kb = k + (size_t)bh * Tx * Dx;
    const float* vb = v + (size_t)bh * Tx * Dx;

    // Load Q tile (64x64): 1024 float4s, 4 per thread
#pragma unroll
    for (int l = 0; l < 4; l++) {
        int f  = tid + l * 256;
        int r  = f >> 4;
        int c4 = (f & 15) * 4;
        float4 qv = *(const float4*)&qb[(size_t)(q0 + r) * Dx + c4];
        *(float4*)&Qs[r * DP + c4] = qv;
    }

    float mo[4], l_[4], acc[4][4];
#pragma unroll
    for (int i = 0; i < 4; i++) {
        mo[i] = -1e30f; l_[i] = 0.0f;
#pragma unroll
        for (int j = 0; j < 4; j++) acc[i][j] = 0.0f;
    }

    const int nblk = q0 / AN + 1;
    const float scale = 0.125f;  // 1/sqrt(64)

    for (int jb = 0; jb < nblk; jb++) {
        const int j0 = jb * AN;
        __syncthreads();   // protect Ks/Vs/Ps reuse
        // Load K,V tiles
#pragma unroll
        for (int l = 0; l < 4; l++) {
            int f  = tid + l * 256;
            int r  = f >> 4;
            int c4 = (f & 15) * 4;
            *(float4*)&Ks[r * DP + c4] = *(const float4*)&kb[(size_t)(j0 + r) * Dx + c4];
            *(float4*)&Vs[r * DP + c4] = *(const float4*)&vb[(size_t)(j0 + r) * Dx + c4];
        }
        __syncthreads();

        // S = Q @ K^T  (thread owns rows 4ty..+3, cols 4tx..+3)
        float s[4][4];
#pragma unroll
        for (int i = 0; i < 4; i++)
#pragma unroll
            for (int j = 0; j < 4; j++) s[i][j] = 0.0f;

#pragma unroll
        for (int d = 0; d < Dx; d += 4) {
            float4 qv[4], kv[4];
#pragma unroll
            for (int i = 0; i < 4; i++) qv[i] = *(const float4*)&Qs[(4 * ty + i) * DP + d];
#pragma unroll
            for (int i = 0; i < 4; i++) kv[i] = *(const float4*)&Ks[(4 * tx + i) * DP + d];
#pragma unroll
            for (int i = 0; i < 4; i++)
#pragma unroll
                for (int j = 0; j < 4; j++) {
                    s[i][j] = fmaf(qv[i].x, kv[j].x, s[i][j]);
                    s[i][j] = fmaf(qv[i].y, kv[j].y, s[i][j]);
                    s[i][j] = fmaf(qv[i].z, kv[j].z, s[i][j]);
                    s[i][j] = fmaf(qv[i].w, kv[j].w, s[i][j]);
                }
        }

        const bool need_mask = (j0 + AN - 1 > q0);
#pragma unroll
        for (int i = 0; i < 4; i++) {
            int qrow = q0 + 4 * ty + i;
#pragma unroll
            for (int j = 0; j < 4; j++) {
                float sv = s[i][j] * scale;
                if (need_mask && (j0 + 4 * tx + j > qrow)) sv = -1e30f;
                s[i][j] = sv;
            }
        }

        // Online softmax update per row
#pragma unroll
        for (int i = 0; i < 4; i++) {
            float mt = fmaxf(fmaxf(s[i][0], s[i][1]), fmaxf(s[i][2], s[i][3]));
#pragma unroll
            for (int off = 8; off >= 1; off >>= 1)
                mt = fmaxf(mt, __shfl_xor_sync(0xffffffffu, mt, off, 16));
            float mn = fmaxf(mo[i], mt);
            float fac = __expf(mo[i] - mn);
            float su = 0.0f;
#pragma unroll
            for (int j = 0; j < 4; j++) {
                float p = __expf(s[i][j] - mn);
                s[i][j] = p;
                su += p;
            }
#pragma unroll
            for (int off = 8; off >= 1; off >>= 1)
                su += __shfl_xor_sync(0xffffffffu, su, off, 16);
            l_[i] = l_[i] * fac + su;
            mo[i] = mn;
#pragma unroll
            for (int j = 0; j < 4; j++) acc[i][j] *= fac;
        }

        // Stage P to smem
#pragma unroll
        for (int i = 0; i < 4; i++) {
            float4 pv = make_float4(s[i][0], s[i][1], s[i][2], s[i][3]);
            *(float4*)&Ps[(4 * ty + i) * NP + 4 * tx] = pv;
        }
        __syncthreads();

        // acc += P @ V  (thread owns out rows 4ty..+3, cols 4tx..+3)
#pragma unroll
        for (int c = 0; c < AN; c += 4) {
            float4 pv[4];
#pragma unroll
            for (int i = 0; i < 4; i++) pv[i] = *(const float4*)&Ps[(4 * ty + i) * NP + c];
#pragma unroll
            for (int cc = 0; cc < 4; cc++) {
                float4 vv = *(const float4*)&Vs[(c + cc) * DP + 4 * tx];
#pragma unroll
                for (int i = 0; i < 4; i++) {
                    float p = (cc == 0) ? pv[i].x : (cc == 1) ? pv[i].y : (cc == 2) ? pv[i].z : pv[i].w;
                    acc[i][0] = fmaf(p, vv.x, acc[i][0]);
                    acc[i][1] = fmaf(p, vv.y, acc[i][1]);
                    acc[i][2] = fmaf(p, vv.z, acc[i][2]);
                    acc[i][3] = fmaf(p, vv.w, acc[i][3]);
                }
            }
        }
    }

    // Epilogue: write [B,T,C]
    const int b_ = bh >> 4;
    const int h_ = bh & 15;
#pragma unroll
    for (int i = 0; i < 4; i++) {
        float inv = 1.0f / l_[i];
        int row = q0 + 4 * ty + i;
#pragma unroll
        for (int j = 0; j < 4; j++) {
            y[((size_t)b_ * Tx + row) * Cx + h_ * Dx + 4 * tx + j] = acc[i][j] * inv;
        }
    }
}

// ---------------------------------------------------------------------------
extern "C" void kernel_launch(void* const* d_in, const int* in_sizes, int n_in,
                              void* d_out, int out_size)
{
    const float* x  = (const float*)d_in[0];
    // d_in[1] = att_mask (int32 tril) — structurally causal, handled in-kernel
    const float* wq = (const float*)d_in[2];
    const float* bq = (const float*)d_in[3];
    const float* wk = (const float*)d_in[4];
    const float* bk = (const float*)d_in[5];
    const float* wv = (const float*)d_in[6];
    const float* bv = (const float*)d_in[7];
    const float* wp = (const float*)d_in[8];
    const float* bp = (const float*)d_in[9];
    float* out = (float*)d_out;

    float *qp, *kp, *vp, *yp;
    cudaGetSymbolAddress((void**)&qp, g_q);
    cudaGetSymbolAddress((void**)&kp, g_k);
    cudaGetSymbolAddress((void**)&vp, g_v);
    cudaGetSymbolAddress((void**)&yp, g_y);

    dim3 gg(Cx / 128, Mrows / 128);   // (8, 32)

    sgemm_kernel<<<gg, 256>>>(x, wq, bq, qp, 1);
    sgemm_kernel<<<gg, 256>>>(x, wk, bk, kp, 1);
    sgemm_kernel<<<gg, 256>>>(x, wv, bv, vp, 1);

    const int smem_bytes = 4 * 64 * 68 * (int)sizeof(float);  // 69632
    cudaFuncSetAttribute(attn_kernel, cudaFuncAttributeMaxDynamicSharedMemorySize, smem_bytes);
    attn_kernel<<<dim3(Tx / 64, Bx * Hx), 256, smem_bytes>>>(qp, kp, vp, yp);

    sgemm_kernel<<<gg, 256>>>(yp, wp, bp, out, 0);
}

// round 5
// speedup vs baseline: 1.3608x; 1.3608x over previous
#include <cuda_runtime.h>
#include <cstdint>

// Problem constants
#define Bx 2
#define Tx 2048
#define Cx 1024
#define Hx 16
#define Dx 64
#define Mrows (Bx*Tx)   // 4096

// Scratch in __device__ globals (no allocations allowed)
__device__ float g_q[(size_t)Bx*Hx*Tx*Dx];   // [B,H,T,D]
__device__ float g_k[(size_t)Bx*Hx*Tx*Dx];
__device__ float g_v[(size_t)Bx*Hx*Tx*Dx];
__device__ float g_y[(size_t)Mrows*Cx];      // [B*T, C]

__device__ __forceinline__ uint32_t smem_u32(const void* p) {
    uint32_t a;
    asm("{ .reg .u64 t; cvta.to.shared.u64 t, %1; cvt.u32.u64 %0, t; }" : "=r"(a) : "l"(p));
    return a;
}
__device__ __forceinline__ uint32_t f2tf32(float f) {
    uint32_t u;
    asm("cvt.rna.tf32.f32 %0, %1;" : "=r"(u) : "f"(f));
    return u;
}

// ---------------------------------------------------------------------------
// tf32 mma.sync GEMM: out[4096,1024] = X[4096,1024] @ W[1024,1024]^T + bias
// CTA tile 128x128, BK=32, 8 warps (2x4) each computing 64x32.
// Double-buffered cp.async. split==1: scatter [B,H,T,D]; else flat [M,C].
// ---------------------------------------------------------------------------
__global__ __launch_bounds__(256, 2) void mma_gemm(
    const float* __restrict__ X, const float* __restrict__ W,
    const float* __restrict__ bias, float* __restrict__ out, int split)
{
    constexpr int NK = 32;                 // 1024/32 k-tiles
    constexpr int LDA = 36;                // padded row stride (floats)
    extern __shared__ float smf[];
    const uint32_t sb = smem_u32(smf);

    const int tid = threadIdx.x;
    const int wid = tid >> 5, lane = tid & 31;
    const int wm = wid >> 2, wn = wid & 3;
    const int bm = blockIdx.y * 128, bn = blockIdx.x * 128;

    const float* Xb = X + (size_t)bm * 1024;
    const float* Wb = W + (size_t)bn * 1024;

    float acc[4][4][4];
#pragma unroll
    for (int mt = 0; mt < 4; mt++)
#pragma unroll
        for (int nt = 0; nt < 4; nt++)
#pragma unroll
            for (int r = 0; r < 4; r++) acc[mt][nt][r] = 0.0f;

    // Per stage: A = 128x32 @ stride 36 = 18432B; B same. Stage = 36864B.
    auto load_stage = [&](int s, int kc) {
        uint32_t A = sb + (uint32_t)s * 36864u;
        uint32_t B = A + 18432u;
        const float* xs = Xb + kc * 32;
        const float* ws = Wb + kc * 32;
#pragma unroll
        for (int i = 0; i < 4; i++) {
            int f = tid + i * 256;         // 0..1023 16B chunks
            int r = f >> 3;                // row 0..127
            int c4 = (f & 7) * 4;          // float col 0,4,..,28
            uint32_t off = (uint32_t)(r * (LDA * 4) + c4 * 4);
            asm volatile("cp.async.cg.shared.global [%0], [%1], 16;"
                         :: "r"(A + off), "l"(xs + (size_t)r * 1024 + c4) : "memory");
            asm volatile("cp.async.cg.shared.global [%0], [%1], 16;"
                         :: "r"(B + off), "l"(ws + (size_t)r * 1024 + c4) : "memory");
        }
        asm volatile("cp.async.commit_group;" ::: "memory");
    };

    load_stage(0, 0);

    for (int k = 0; k < NK; k++) {
        if (k + 1 < NK) {
            load_stage((k + 1) & 1, k + 1);
            asm volatile("cp.async.wait_group 1;" ::: "memory");
        } else {
            asm volatile("cp.async.wait_group 0;" ::: "memory");
        }
        __syncthreads();

        const float* A = smf + (k & 1) * 9216;
        const float* B = A + 4608;
        const int lr = lane >> 2;          // 0..7
        const int lc = lane & 3;           // 0..3

#pragma unroll
        for (int kk = 0; kk < 4; kk++) {
            uint32_t af[4][4], bf[4][2];
            const int c = kk * 8 + lc;
#pragma unroll
            for (int mt = 0; mt < 4; mt++) {
                int r0 = wm * 64 + mt * 16 + lr;
                af[mt][0] = f2tf32(A[r0 * LDA + c]);
                af[mt][1] = f2tf32(A[(r0 + 8) * LDA + c]);
                af[mt][2] = f2tf32(A[r0 * LDA + c + 4]);
                af[mt][3] = f2tf32(A[(r0 + 8) * LDA + c + 4]);
            }
#pragma unroll
            for (int nt = 0; nt < 4; nt++) {
                int n0 = wn * 32 + nt * 8 + lr;
                bf[nt][0] = f2tf32(B[n0 * LDA + c]);
                bf[nt][1] = f2tf32(B[n0 * LDA + c + 4]);
            }
#pragma unroll
            for (int mt = 0; mt < 4; mt++)
#pragma unroll
                for (int nt = 0; nt < 4; nt++) {
                    asm volatile(
                        "mma.sync.aligned.m16n8k8.row.col.f32.tf32.tf32.f32 "
                        "{%0,%1,%2,%3}, {%4,%5,%6,%7}, {%8,%9}, {%0,%1,%2,%3};"
                        : "+f"(acc[mt][nt][0]), "+f"(acc[mt][nt][1]),
                          "+f"(acc[mt][nt][2]), "+f"(acc[mt][nt][3])
                        : "r"(af[mt][0]), "r"(af[mt][1]), "r"(af[mt][2]), "r"(af[mt][3]),
                          "r"(bf[nt][0]), "r"(bf[nt][1]));
                }
        }
        __syncthreads();
    }

    // Epilogue. c0:(r,c) c1:(r,c+1) c2:(r+8,c) c3:(r+8,c+1)
    const int lr = lane >> 2, lc = lane & 3;
#pragma unroll
    for (int mt = 0; mt < 4; mt++) {
#pragma unroll
        for (int nt = 0; nt < 4; nt++) {
            int row = bm + wm * 64 + mt * 16 + lr;
            int col = bn + wn * 32 + nt * 8 + lc * 2;
            float b0 = __ldg(bias + col), b1 = __ldg(bias + col + 1);
            float2 v0 = make_float2(acc[mt][nt][0] + b0, acc[mt][nt][1] + b1);
            float2 v1 = make_float2(acc[mt][nt][2] + b0, acc[mt][nt][3] + b1);
            if (split) {
                int h_ = col >> 6, d_ = col & 63;
                int b_ = row >> 11, t_ = row & 2047;
                size_t base = (((size_t)(b_ * Hx + h_) * Tx) + t_) * Dx + d_;
                *(float2*)(out + base) = v0;
                int t2 = (row + 8) & 2047;   // row+8 stays in same b_ (rows mult of 16)
                size_t base2 = (((size_t)(b_ * Hx + h_) * Tx) + t2) * Dx + d_;
                *(float2*)(out + base2) = v1;
            } else {
                *(float2*)(out + (size_t)row * Cx + col) = v0;
                *(float2*)(out + (size_t)(row + 8) * Cx + col) = v1;
            }
        }
    }
}

// ---------------------------------------------------------------------------
// Flash-attention, fp32 SIMT, 128q x 128k tiles.
// 256 threads as 16x16: ty owns rows 8ty..8ty+7.
// S cols: strided ownership col = tx + 16*j. O cols: tx*4..tx*4+3.
// ---------------------------------------------------------------------------
__global__ __launch_bounds__(256) void attn_kernel(
    const float* __restrict__ q, const float* __restrict__ k,
    const float* __restrict__ v, float* __restrict__ y)
{
    constexpr int DP = 68, NP = 132;
    extern __shared__ float sm[];
    float* Qs = sm;                    // 128*DP
    float* Ks = Qs + 128 * DP;
    float* Vs = Ks + 128 * DP;
    float* Ps = Vs + 128 * DP;         // 128*NP

    const int bh = blockIdx.y;
    const int q0 = blockIdx.x * 128;
    const int tid = threadIdx.x;
    const int tx = tid & 15;
    const int ty = tid >> 4;
    const float* qb = q + (size_t)bh * Tx * Dx;
    const float* kb = k + (size_t)bh * Tx * Dx;
    const float* vb = v + (size_t)bh * Tx * Dx;

#pragma unroll
    for (int l = 0; l < 8; l++) {
        int f = tid + l * 256;
        int r = f >> 4, c4 = (f & 15) * 4;
        *(float4*)&Qs[r * DP + c4] = *(const float4*)&qb[(size_t)(q0 + r) * Dx + c4];
    }

    float mo[8], l_[8], acc[8][4];
#pragma unroll
    for (int i = 0; i < 8; i++) {
        mo[i] = -1e30f; l_[i] = 0.0f;
#pragma unroll
        for (int j = 0; j < 4; j++) acc[i][j] = 0.0f;
    }

    const int nblk = blockIdx.x + 1;
    const float scale = 0.125f;        // 1/sqrt(64)

    for (int jb = 0; jb < nblk; jb++) {
        const int j0 = jb * 128;
        __syncthreads();
#pragma unroll
        for (int l = 0; l < 8; l++) {
            int f = tid + l * 256;
            int r = f >> 4, c4 = (f & 15) * 4;
            *(float4*)&Ks[r * DP + c4] = *(const float4*)&kb[(size_t)(j0 + r) * Dx + c4];
            *(float4*)&Vs[r * DP + c4] = *(const float4*)&vb[(size_t)(j0 + r) * Dx + c4];
        }
        __syncthreads();

        float s[8][8];
#pragma unroll
        for (int i = 0; i < 8; i++)
#pragma unroll
            for (int j = 0; j < 8; j++) s[i][j] = 0.0f;

#pragma unroll
        for (int d = 0; d < Dx; d += 4) {
            float4 qv[8];
#pragma unroll
            for (int i = 0; i < 8; i++) qv[i] = *(const float4*)&Qs[(8 * ty + i) * DP + d];
#pragma unroll
            for (int j = 0; j < 8; j++) {
                float4 kv = *(const float4*)&Ks[(tx + 16 * j) * DP + d];
#pragma unroll
                for (int i = 0; i < 8; i++) {
                    s[i][j] = fmaf(qv[i].x, kv.x, s[i][j]);
                    s[i][j] = fmaf(qv[i].y, kv.y, s[i][j]);
                    s[i][j] = fmaf(qv[i].z, kv.z, s[i][j]);
                    s[i][j] = fmaf(qv[i].w, kv.w, s[i][j]);
                }
            }
        }

        const bool dm = (jb == blockIdx.x);
#pragma unroll
        for (int i = 0; i < 8; i++) {
            int qrow = q0 + 8 * ty + i;
#pragma unroll
            for (int j = 0; j < 8; j++) {
                float sv = s[i][j] * scale;
                if (dm && (j0 + tx + 16 * j > qrow)) sv = -1e30f;
                s[i][j] = sv;
            }
        }

#pragma unroll
        for (int i = 0; i < 8; i++) {
            float mt = s[i][0];
#pragma unroll
            for (int j = 1; j < 8; j++) mt = fmaxf(mt, s[i][j]);
#pragma unroll
            for (int off = 8; off >= 1; off >>= 1)
                mt = fmaxf(mt, __shfl_xor_sync(0xffffffffu, mt, off, 16));
            float mn = fmaxf(mo[i], mt);
            float fac = __expf(mo[i] - mn);
            float su = 0.0f;
#pragma unroll
            for (int j = 0; j < 8; j++) {
                float p = __expf(s[i][j] - mn);
                s[i][j] = p;
                su += p;
            }
#pragma unroll
            for (int off = 8; off >= 1; off >>= 1)
                su += __shfl_xor_sync(0xffffffffu, su, off, 16);
            l_[i] = l_[i] * fac + su;
            mo[i] = mn;
#pragma unroll
            for (int j = 0; j < 4; j++) acc[i][j] *= fac;
        }

#pragma unroll
        for (int i = 0; i < 8; i++)
#pragma unroll
            for (int j = 0; j < 8; j++)
                Ps[(8 * ty + i) * NP + tx + 16 * j] = s[i][j];
        __syncthreads();

#pragma unroll
        for (int c = 0; c < 128; c += 4) {
            float4 pv[8];
#pragma unroll
            for (int i = 0; i < 8; i++) pv[i] = *(const float4*)&Ps[(8 * ty + i) * NP + c];
#pragma unroll
            for (int cc = 0; cc < 4; cc++) {
                float4 vv = *(const float4*)&Vs[(c + cc) * DP + 4 * tx];
#pragma unroll
                for (int i = 0; i < 8; i++) {
                    float p = (cc == 0) ? pv[i].x : (cc == 1) ? pv[i].y : (cc == 2) ? pv[i].z : pv[i].w;
                    acc[i][0] = fmaf(p, vv.x, acc[i][0]);
                    acc[i][1] = fmaf(p, vv.y, acc[i][1]);
                    acc[i][2] = fmaf(p, vv.z, acc[i][2]);
                    acc[i][3] = fmaf(p, vv.w, acc[i][3]);
                }
            }
        }
    }

    const int b_ = bh >> 4;
    const int h_ = bh & 15;
#pragma unroll
    for (int i = 0; i < 8; i++) {
        float inv = 1.0f / l_[i];
        int rowg = q0 + 8 * ty + i;
        float4 o;
        o.x = acc[i][0] * inv; o.y = acc[i][1] * inv;
        o.z = acc[i][2] * inv; o.w = acc[i][3] * inv;
        *(float4*)&y[((size_t)b_ * Tx + rowg) * Cx + h_ * Dx + 4 * tx] = o;
    }
}

// ---------------------------------------------------------------------------
extern "C" void kernel_launch(void* const* d_in, const int* in_sizes, int n_in,
                              void* d_out, int out_size)
{
    const float* x  = (const float*)d_in[0];
    // d_in[1] = att_mask (causal tril) — handled structurally in-kernel
    const float* wq = (const float*)d_in[2];
    const float* bq = (const float*)d_in[3];
    const float* wk = (const float*)d_in[4];
    const float* bk = (const float*)d_in[5];
    const float* wv = (const float*)d_in[6];
    const float* bv = (const float*)d_in[7];
    const float* wp = (const float*)d_in[8];
    const float* bp = (const float*)d_in[9];
    float* out = (float*)d_out;

    float *qp, *kp, *vp, *yp;
    cudaGetSymbolAddress((void**)&qp, g_q);
    cudaGetSymbolAddress((void**)&kp, g_k);
    cudaGetSymbolAddress((void**)&vp, g_v);
    cudaGetSymbolAddress((void**)&yp, g_y);

    const int gemm_smem = 2 * 36864;   // 73728 (2 stages)
    cudaFuncSetAttribute(mma_gemm, cudaFuncAttributeMaxDynamicSharedMemorySize, gemm_smem);
    dim3 gg(Cx / 128, Mrows / 128);    // (8, 32)

    mma_gemm<<<gg, 256, gemm_smem>>>(x, wq, bq, qp, 1);
    mma_gemm<<<gg, 256, gemm_smem>>>(x, wk, bk, kp, 1);
    mma_gemm<<<gg, 256, gemm_smem>>>(x, wv, bv, vp, 1);

    const int attn_smem = (3 * 128 * 68 + 128 * 132) * (int)sizeof(float);  // 172032
    cudaFuncSetAttribute(attn_kernel, cudaFuncAttributeMaxDynamicSharedMemorySize, attn_smem);
    attn_kernel<<<dim3(Tx / 128, Bx * Hx), 256, attn_smem>>>(qp, kp, vp, yp);

    mma_gemm<<<gg, 256, gemm_smem>>>(yp, wp, bp, out, 0);
}

// round 6
// speedup vs baseline: 4.2287x; 3.1074x over previous
#include <cuda_runtime.h>
#include <cstdint>

// Problem constants
#define Bx 2
#define Tx 2048
#define Cx 1024
#define Hx 16
#define Dx 64
#define Mrows (Bx*Tx)   // 4096

// Scratch in __device__ globals (no allocations allowed)
__device__ float g_q[(size_t)Bx*Hx*Tx*Dx];   // [B,H,T,D]
__device__ float g_k[(size_t)Bx*Hx*Tx*Dx];
__device__ float g_v[(size_t)Bx*Hx*Tx*Dx];
__device__ float g_y[(size_t)Mrows*Cx];      // [B*T, C]

__device__ __forceinline__ uint32_t smem_u32(const void* p) {
    uint32_t a;
    asm("{ .reg .u64 t; cvta.to.shared.u64 t, %1; cvt.u32.u64 %0, t; }" : "=r"(a) : "l"(p));
    return a;
}
__device__ __forceinline__ uint32_t f2tf32(float f) {
    uint32_t u;
    asm("cvt.rna.tf32.f32 %0, %1;" : "=r"(u) : "f"(f));
    return u;
}
#define MMA_TF32(C, A0,A1,A2,A3, B0,B1) \
    asm volatile("mma.sync.aligned.m16n8k8.row.col.f32.tf32.tf32.f32 " \
        "{%0,%1,%2,%3}, {%4,%5,%6,%7}, {%8,%9}, {%0,%1,%2,%3};" \
        : "+f"((C)[0]), "+f"((C)[1]), "+f"((C)[2]), "+f"((C)[3]) \
        : "r"(A0), "r"(A1), "r"(A2), "r"(A3), "r"(B0), "r"(B1))

// ---------------------------------------------------------------------------
// tf32 mma.sync GEMM: out[4096,1024] = X[4096,1024] @ W[1024,1024]^T + bias
// CTA tile 128x128, BK=32, 8 warps (2x4) each computing 64x32.
// Double-buffered cp.async. split==1: scatter [B,H,T,D]; else flat [M,C].
// ---------------------------------------------------------------------------
__global__ __launch_bounds__(256, 2) void mma_gemm(
    const float* __restrict__ X, const float* __restrict__ W,
    const float* __restrict__ bias, float* __restrict__ out, int split)
{
    constexpr int NK = 32;
    constexpr int LDA = 36;
    extern __shared__ float smf[];
    const uint32_t sb = smem_u32(smf);

    const int tid = threadIdx.x;
    const int wid = tid >> 5, lane = tid & 31;
    const int wm = wid >> 2, wn = wid & 3;
    const int bm = blockIdx.y * 128, bn = blockIdx.x * 128;

    const float* Xb = X + (size_t)bm * 1024;
    const float* Wb = W + (size_t)bn * 1024;

    float acc[4][4][4];
#pragma unroll
    for (int mt = 0; mt < 4; mt++)
#pragma unroll
        for (int nt = 0; nt < 4; nt++)
#pragma unroll
            for (int r = 0; r < 4; r++) acc[mt][nt][r] = 0.0f;

    auto load_stage = [&](int s, int kc) {
        uint32_t A = sb + (uint32_t)s * 36864u;
        uint32_t B = A + 18432u;
        const float* xs = Xb + kc * 32;
        const float* ws = Wb + kc * 32;
#pragma unroll
        for (int i = 0; i < 4; i++) {
            int f = tid + i * 256;
            int r = f >> 3;
            int c4 = (f & 7) * 4;
            uint32_t off = (uint32_t)(r * (LDA * 4) + c4 * 4);
            asm volatile("cp.async.cg.shared.global [%0], [%1], 16;"
                         :: "r"(A + off), "l"(xs + (size_t)r * 1024 + c4) : "memory");
            asm volatile("cp.async.cg.shared.global [%0], [%1], 16;"
                         :: "r"(B + off), "l"(ws + (size_t)r * 1024 + c4) : "memory");
        }
        asm volatile("cp.async.commit_group;" ::: "memory");
    };

    load_stage(0, 0);

    for (int k = 0; k < NK; k++) {
        if (k + 1 < NK) {
            load_stage((k + 1) & 1, k + 1);
            asm volatile("cp.async.wait_group 1;" ::: "memory");
        } else {
            asm volatile("cp.async.wait_group 0;" ::: "memory");
        }
        __syncthreads();

        const float* A = smf + (k & 1) * 9216;
        const float* B = A + 4608;
        const int lr = lane >> 2;
        const int lc = lane & 3;

#pragma unroll
        for (int kk = 0; kk < 4; kk++) {
            uint32_t af[4][4], bf[4][2];
            const int c = kk * 8 + lc;
#pragma unroll
            for (int mt = 0; mt < 4; mt++) {
                int r0 = wm * 64 + mt * 16 + lr;
                af[mt][0] = f2tf32(A[r0 * LDA + c]);
                af[mt][1] = f2tf32(A[(r0 + 8) * LDA + c]);
                af[mt][2] = f2tf32(A[r0 * LDA + c + 4]);
                af[mt][3] = f2tf32(A[(r0 + 8) * LDA + c + 4]);
            }
#pragma unroll
            for (int nt = 0; nt < 4; nt++) {
                int n0 = wn * 32 + nt * 8 + lr;
                bf[nt][0] = f2tf32(B[n0 * LDA + c]);
                bf[nt][1] = f2tf32(B[n0 * LDA + c + 4]);
            }
#pragma unroll
            for (int mt = 0; mt < 4; mt++)
#pragma unroll
                for (int nt = 0; nt < 4; nt++)
                    MMA_TF32(acc[mt][nt], af[mt][0], af[mt][1], af[mt][2], af[mt][3],
                             bf[nt][0], bf[nt][1]);
        }
        __syncthreads();
    }

    const int lr = lane >> 2, lc = lane & 3;
#pragma unroll
    for (int mt = 0; mt < 4; mt++) {
#pragma unroll
        for (int nt = 0; nt < 4; nt++) {
            int row = bm + wm * 64 + mt * 16 + lr;
            int col = bn + wn * 32 + nt * 8 + lc * 2;
            float b0 = __ldg(bias + col), b1 = __ldg(bias + col + 1);
            float2 v0 = make_float2(acc[mt][nt][0] + b0, acc[mt][nt][1] + b1);
            float2 v1 = make_float2(acc[mt][nt][2] + b0, acc[mt][nt][3] + b1);
            if (split) {
                int h_ = col >> 6, d_ = col & 63;
                int b_ = row >> 11, t_ = row & 2047;
                size_t base = (((size_t)(b_ * Hx + h_) * Tx) + t_) * Dx + d_;
                *(float2*)(out + base) = v0;
                int t2 = (row + 8) & 2047;
                size_t base2 = (((size_t)(b_ * Hx + h_) * Tx) + t2) * Dx + d_;
                *(float2*)(out + base2) = v1;
            } else {
                *(float2*)(out + (size_t)row * Cx + col) = v0;
                *(float2*)(out + (size_t)(row + 8) * Cx + col) = v1;
            }
        }
    }
}

// ---------------------------------------------------------------------------
// Tensor-core flash attention (tf32 mma.sync).
// CTA = 128 q-rows, 8 warps, warp owns 16 rows. K-tiles of 128.
// Q/K/V staged in smem as pre-converted tf32 bits. P per-warp smem strip.
// All fragment LDS bank-conflict-free by construction.
// ---------------------------------------------------------------------------
__global__ __launch_bounds__(256) void attn_mma(
    const float* __restrict__ q, const float* __restrict__ k,
    const float* __restrict__ v, float* __restrict__ y)
{
    constexpr int QP = 68, KP = 68, VP = 72, PP = 132;
    extern __shared__ uint32_t sw[];
    uint32_t* Qs = sw;                 // 128*QP
    uint32_t* Ks = Qs + 128 * QP;      // 128*KP
    uint32_t* Vs = Ks + 128 * KP;      // 128*VP
    uint32_t* Ps = Vs + 128 * VP;      // 128*PP (8 warps x 16 rows)

    const int bh = blockIdx.y;
    const int qt = gridDim.x - 1 - blockIdx.x;   // heaviest tiles first
    const int q0 = qt * 128;
    const int tid = threadIdx.x;
    const int wid = tid >> 5, lane = tid & 31;
    const int lr = lane >> 2, lc = lane & 3;
    const float* qb = q + (size_t)bh * Tx * Dx;
    const float* kb = k + (size_t)bh * Tx * Dx;
    const float* vb = v + (size_t)bh * Tx * Dx;
    uint32_t* Pw = Ps + wid * 16 * PP;

    // Load Q tile (scale 1/8 folded in; exact pow2), cvt to tf32 bits
#pragma unroll
    for (int l = 0; l < 8; l++) {
        int f = tid + l * 256;
        int r = f >> 4, c4 = (f & 15) * 4;
        float4 t = *(const float4*)&qb[(size_t)(q0 + r) * Dx + c4];
        Qs[r * QP + c4 + 0] = f2tf32(t.x * 0.125f);
        Qs[r * QP + c4 + 1] = f2tf32(t.y * 0.125f);
        Qs[r * QP + c4 + 2] = f2tf32(t.z * 0.125f);
        Qs[r * QP + c4 + 3] = f2tf32(t.w * 0.125f);
    }

    float m0 = -1e30f, m1 = -1e30f, l0 = 0.0f, l1 = 0.0f;
    float o[8][4];
#pragma unroll
    for (int dn = 0; dn < 8; dn++)
#pragma unroll
        for (int r = 0; r < 4; r++) o[dn][r] = 0.0f;

    for (int jb = 0; jb <= qt; jb++) {
        const int j0 = jb * 128;
        __syncthreads();               // prior iter done reading Ks/Vs
#pragma unroll
        for (int l = 0; l < 8; l++) {
            int f = tid + l * 256;
            int r = f >> 4, c4 = (f & 15) * 4;
            float4 tk = *(const float4*)&kb[(size_t)(j0 + r) * Dx + c4];
            float4 tv = *(const float4*)&vb[(size_t)(j0 + r) * Dx + c4];
            Ks[r * KP + c4 + 0] = f2tf32(tk.x);
            Ks[r * KP + c4 + 1] = f2tf32(tk.y);
            Ks[r * KP + c4 + 2] = f2tf32(tk.z);
            Ks[r * KP + c4 + 3] = f2tf32(tk.w);
            Vs[r * VP + c4 + 0] = f2tf32(tv.x);
            Vs[r * VP + c4 + 1] = f2tf32(tv.y);
            Vs[r * VP + c4 + 2] = f2tf32(tv.z);
            Vs[r * VP + c4 + 3] = f2tf32(tv.w);
        }
        __syncthreads();

        // S = Q @ K^T : warp rows [wid*16, wid*16+16), 16 n-tiles of 8 keys
        float s[16][4];
#pragma unroll
        for (int nt = 0; nt < 16; nt++)
#pragma unroll
            for (int r = 0; r < 4; r++) s[nt][r] = 0.0f;

#pragma unroll
        for (int ks = 0; ks < 8; ks++) {
            uint32_t a0 = Qs[(wid * 16 + lr) * QP + ks * 8 + lc];
            uint32_t a1 = Qs[(wid * 16 + lr + 8) * QP + ks * 8 + lc];
            uint32_t a2 = Qs[(wid * 16 + lr) * QP + ks * 8 + lc + 4];
            uint32_t a3 = Qs[(wid * 16 + lr + 8) * QP + ks * 8 + lc + 4];
#pragma unroll
            for (int nt = 0; nt < 16; nt++) {
                uint32_t b0 = Ks[(nt * 8 + lr) * KP + ks * 8 + lc];
                uint32_t b1 = Ks[(nt * 8 + lr) * KP + ks * 8 + lc + 4];
                MMA_TF32(s[nt], a0, a1, a2, a3, b0, b1);
            }
        }

        // Causal mask (diagonal tile only)
        if (jb == qt) {
            int r0g = q0 + wid * 16 + lr;
            int r1g = r0g + 8;
#pragma unroll
            for (int nt = 0; nt < 16; nt++) {
                int c0g = j0 + nt * 8 + lc * 2;
                if (c0g > r0g)     s[nt][0] = -1e30f;
                if (c0g + 1 > r0g) s[nt][1] = -1e30f;
                if (c0g > r1g)     s[nt][2] = -1e30f;
                if (c0g + 1 > r1g) s[nt][3] = -1e30f;
            }
        }

        // Row max over tile (rows lr and lr+8 of warp strip)
        float tm0 = -1e30f, tm1 = -1e30f;
#pragma unroll
        for (int nt = 0; nt < 16; nt++) {
            tm0 = fmaxf(tm0, fmaxf(s[nt][0], s[nt][1]));
            tm1 = fmaxf(tm1, fmaxf(s[nt][2], s[nt][3]));
        }
        tm0 = fmaxf(tm0, __shfl_xor_sync(0xffffffffu, tm0, 1));
        tm0 = fmaxf(tm0, __shfl_xor_sync(0xffffffffu, tm0, 2));
        tm1 = fmaxf(tm1, __shfl_xor_sync(0xffffffffu, tm1, 1));
        tm1 = fmaxf(tm1, __shfl_xor_sync(0xffffffffu, tm1, 2));

        float mn0 = fmaxf(m0, tm0), mn1 = fmaxf(m1, tm1);
        float f0 = __expf(m0 - mn0), f1 = __expf(m1 - mn1);
        float su0 = 0.0f, su1 = 0.0f;
#pragma unroll
        for (int nt = 0; nt < 16; nt++) {
            float p0 = __expf(s[nt][0] - mn0);
            float p1 = __expf(s[nt][1] - mn0);
            float p2 = __expf(s[nt][2] - mn1);
            float p3 = __expf(s[nt][3] - mn1);
            su0 += p0 + p1;
            su1 += p2 + p3;
            Pw[lr * PP + nt * 8 + lc * 2]           = f2tf32(p0);
            Pw[lr * PP + nt * 8 + lc * 2 + 1]       = f2tf32(p1);
            Pw[(lr + 8) * PP + nt * 8 + lc * 2]     = f2tf32(p2);
            Pw[(lr + 8) * PP + nt * 8 + lc * 2 + 1] = f2tf32(p3);
        }
        su0 += __shfl_xor_sync(0xffffffffu, su0, 1);
        su0 += __shfl_xor_sync(0xffffffffu, su0, 2);
        su1 += __shfl_xor_sync(0xffffffffu, su1, 1);
        su1 += __shfl_xor_sync(0xffffffffu, su1, 2);

        l0 = l0 * f0 + su0;
        l1 = l1 * f1 + su1;
        m0 = mn0; m1 = mn1;
#pragma unroll
        for (int dn = 0; dn < 8; dn++) {
            o[dn][0] *= f0; o[dn][1] *= f0;
            o[dn][2] *= f1; o[dn][3] *= f1;
        }
        __syncwarp();   // P strip visible within warp

        // O += P @ V : 16 k-steps (128 keys), 8 d-tiles (D=64)
#pragma unroll
        for (int ks2 = 0; ks2 < 16; ks2++) {
            uint32_t a0 = Pw[lr * PP + ks2 * 8 + lc];
            uint32_t a1 = Pw[(lr + 8) * PP + ks2 * 8 + lc];
            uint32_t a2 = Pw[lr * PP + ks2 * 8 + lc + 4];
            uint32_t a3 = Pw[(lr + 8) * PP + ks2 * 8 + lc + 4];
#pragma unroll
            for (int dn = 0; dn < 8; dn++) {
                uint32_t b0 = Vs[(ks2 * 8 + lc) * VP + dn * 8 + lr];
                uint32_t b1 = Vs[(ks2 * 8 + lc + 4) * VP + dn * 8 + lr];
                MMA_TF32(o[dn], a0, a1, a2, a3, b0, b1);
            }
        }
        __syncwarp();   // P reads done before next iter overwrites
    }

    // Epilogue: y[B,T,C]
    const int b_ = bh >> 4, h_ = bh & 15;
    const float i0 = 1.0f / l0, i1 = 1.0f / l1;
    const int r0g = q0 + wid * 16 + lr;
#pragma unroll
    for (int dn = 0; dn < 8; dn++) {
        int col = h_ * Dx + dn * 8 + lc * 2;
        float2 w0 = make_float2(o[dn][0] * i0, o[dn][1] * i0);
        float2 w1 = make_float2(o[dn][2] * i1, o[dn][3] * i1);
        *(float2*)&y[((size_t)b_ * Tx + r0g) * Cx + col] = w0;
        *(float2*)&y[((size_t)b_ * Tx + r0g + 8) * Cx + col] = w1;
    }
}

// ---------------------------------------------------------------------------
extern "C" void kernel_launch(void* const* d_in, const int* in_sizes, int n_in,
                              void* d_out, int out_size)
{
    const float* x  = (const float*)d_in[0];
    // d_in[1] = att_mask (causal tril) — handled structurally in-kernel
    const float* wq = (const float*)d_in[2];
    const float* bq = (const float*)d_in[3];
    const float* wk = (const float*)d_in[4];
    const float* bk = (const float*)d_in[5];
    const float* wv = (const float*)d_in[6];
    const float* bv = (const float*)d_in[7];
    const float* wp = (const float*)d_in[8];
    const float* bp = (const float*)d_in[9];
    float* out = (float*)d_out;

    float *qp, *kp, *vp, *yp;
    cudaGetSymbolAddress((void**)&qp, g_q);
    cudaGetSymbolAddress((void**)&kp, g_k);
    cudaGetSymbolAddress((void**)&vp, g_v);
    cudaGetSymbolAddress((void**)&yp, g_y);

    const int gemm_smem = 2 * 36864;   // 73728 (2 stages)
    cudaFuncSetAttribute(mma_gemm, cudaFuncAttributeMaxDynamicSharedMemorySize, gemm_smem);
    dim3 gg(Cx / 128, Mrows / 128);    // (8, 32)

    mma_gemm<<<gg, 256, gemm_smem>>>(x, wq, bq, qp, 1);
    mma_gemm<<<gg, 256, gemm_smem>>>(x, wk, bk, kp, 1);
    mma_gemm<<<gg, 256, gemm_smem>>>(x, wv, bv, vp, 1);

    const int attn_smem = (128 * 68 + 128 * 68 + 128 * 72 + 128 * 132) * 4; // 174080
    cudaFuncSetAttribute(attn_mma, cudaFuncAttributeMaxDynamicSharedMemorySize, attn_smem);
    attn_mma<<<dim3(Tx / 128, Bx * Hx), 256, attn_smem>>>(qp, kp, vp, yp);

    mma_gemm<<<gg, 256, gemm_smem>>>(yp, wp, bp, out, 0);
}

// round 9
// speedup vs baseline: 4.2855x; 1.0134x over previous
#include <cuda_runtime.h>
#include <cstdint>

// Problem constants
#define Bx 2
#define Tx 2048
#define Cx 1024
#define Hx 16
#define Dx 64
#define Mrows (Bx*Tx)   // 4096

// Scratch in __device__ globals (no allocations allowed)
__device__ float g_q[(size_t)Bx*Hx*Tx*Dx];   // [B,H,T,D] (tf32-rounded)
__device__ float g_k[(size_t)Bx*Hx*Tx*Dx];
__device__ float g_v[(size_t)Bx*Hx*Tx*Dx];
__device__ float g_y[(size_t)Mrows*Cx];      // [B*T, C]  (tf32-rounded)
__device__ float g_xr[(size_t)Mrows*Cx];     // tf32-rounded X

__device__ __forceinline__ uint32_t smem_u32(const void* p) {
    uint32_t a;
    asm("{ .reg .u64 t; cvta.to.shared.u64 t, %1; cvt.u32.u64 %0, t; }" : "=r"(a) : "l"(p));
    return a;
}
__device__ __forceinline__ uint32_t f2tf32(float f) {
    uint32_t u;
    asm("cvt.rna.tf32.f32 %0, %1;" : "=r"(u) : "f"(f));
    return u;
}
#define MMA_TF32(C, A0,A1,A2,A3, B0,B1) \
    asm volatile("mma.sync.aligned.m16n8k8.row.col.f32.tf32.tf32.f32 " \
        "{%0,%1,%2,%3}, {%4,%5,%6,%7}, {%8,%9}, {%0,%1,%2,%3};" \
        : "+f"((C)[0]), "+f"((C)[1]), "+f"((C)[2]), "+f"((C)[3]) \
        : "r"(A0), "r"(A1), "r"(A2), "r"(A3), "r"(B0), "r"(B1))

// ---------------------------------------------------------------------------
// tf32 rounding pre-pass
// ---------------------------------------------------------------------------
__global__ __launch_bounds__(256) void round_tf32_kernel(
    const float* __restrict__ in, float* __restrict__ out, int n)
{
    int i = (blockIdx.x * 256 + threadIdx.x) * 4;
    if (i < n) {
        float4 v = *(const float4*)(in + i);
        float4 o;
        o.x = __uint_as_float(f2tf32(v.x));
        o.y = __uint_as_float(f2tf32(v.y));
        o.z = __uint_as_float(f2tf32(v.z));
        o.w = __uint_as_float(f2tf32(v.w));
        *(float4*)(out + i) = o;
    }
}

// ---------------------------------------------------------------------------
// tf32 mma.sync GEMM: out[4096,1024] = X[4096,1024] @ W[1024,1024]^T + bias
// CTA tile 128x128, BK=32, 8 warps (2x4) each computing 64x32.
// 3-stage cp.async pipeline. a_rounded: A already tf32 (skip cvt).
// round_out: round outputs to tf32. split: scatter [B,H,T,D].
// ---------------------------------------------------------------------------
__global__ __launch_bounds__(256, 2) void mma_gemm(
    const float* __restrict__ X, const float* __restrict__ W,
    const float* __restrict__ bias, float* __restrict__ out,
    int split, int a_rounded, int round_out)
{
    constexpr int NK = 32;
    constexpr int LDA = 36;
    constexpr uint32_t STB = 36864u;
    extern __shared__ float smf[];
    const uint32_t sb = smem_u32(smf);

    const int tid = threadIdx.x;
    const int wid = tid >> 5, lane = tid & 31;
    const int wm = wid >> 2, wn = wid & 3;
    const int bm = blockIdx.y * 128, bn = blockIdx.x * 128;

    const float* Xb = X + (size_t)bm * 1024;
    const float* Wb = W + (size_t)bn * 1024;

    float acc[4][4][4];
#pragma unroll
    for (int mt = 0; mt < 4; mt++)
#pragma unroll
        for (int nt = 0; nt < 4; nt++)
#pragma unroll
            for (int r = 0; r < 4; r++) acc[mt][nt][r] = 0.0f;

    auto load_stage = [&](int s, int kc) {
        uint32_t A = sb + (uint32_t)s * STB;
        uint32_t B = A + 18432u;
        const float* xs = Xb + kc * 32;
        const float* ws = Wb + kc * 32;
#pragma unroll
        for (int i = 0; i < 4; i++) {
            int f = tid + i * 256;
            int r = f >> 3;
            int c4 = (f & 7) * 4;
            uint32_t off = (uint32_t)(r * (LDA * 4) + c4 * 4);
            asm volatile("cp.async.cg.shared.global [%0], [%1], 16;"
                         :: "r"(A + off), "l"(xs + (size_t)r * 1024 + c4) : "memory");
            asm volatile("cp.async.cg.shared.global [%0], [%1], 16;"
                         :: "r"(B + off), "l"(ws + (size_t)r * 1024 + c4) : "memory");
        }
        asm volatile("cp.async.commit_group;" ::: "memory");
    };

    load_stage(0, 0);
    load_stage(1, 1);

    for (int k = 0; k < NK; k++) {
        if (k + 2 < NK) {
            load_stage((k + 2) % 3, k + 2);
            asm volatile("cp.async.wait_group 2;" ::: "memory");
        } else if (k + 1 < NK) {
            asm volatile("cp.async.wait_group 1;" ::: "memory");
        } else {
            asm volatile("cp.async.wait_group 0;" ::: "memory");
        }
        __syncthreads();

        const float* A = smf + (k % 3) * 9216;
        const float* B = A + 4608;
        const int lr = lane >> 2;
        const int lc = lane & 3;

#pragma unroll
        for (int kk = 0; kk < 4; kk++) {
            uint32_t af[4][4], bf[4][2];
            const int c = kk * 8 + lc;
#pragma unroll
            for (int mt = 0; mt < 4; mt++) {
                int r0 = wm * 64 + mt * 16 + lr;
                if (a_rounded) {
                    af[mt][0] = __float_as_uint(A[r0 * LDA + c]);
                    af[mt][1] = __float_as_uint(A[(r0 + 8) * LDA + c]);
                    af[mt][2] = __float_as_uint(A[r0 * LDA + c + 4]);
                    af[mt][3] = __float_as_uint(A[(r0 + 8) * LDA + c + 4]);
                } else {
                    af[mt][0] = f2tf32(A[r0 * LDA + c]);
                    af[mt][1] = f2tf32(A[(r0 + 8) * LDA + c]);
                    af[mt][2] = f2tf32(A[r0 * LDA + c + 4]);
                    af[mt][3] = f2tf32(A[(r0 + 8) * LDA + c + 4]);
                }
            }
#pragma unroll
            for (int nt = 0; nt < 4; nt++) {
                int n0 = wn * 32 + nt * 8 + lr;
                bf[nt][0] = f2tf32(B[n0 * LDA + c]);
                bf[nt][1] = f2tf32(B[n0 * LDA + c + 4]);
            }
#pragma unroll
            for (int mt = 0; mt < 4; mt++)
#pragma unroll
                for (int nt = 0; nt < 4; nt++)
                    MMA_TF32(acc[mt][nt], af[mt][0], af[mt][1], af[mt][2], af[mt][3],
                             bf[nt][0], bf[nt][1]);
        }
        __syncthreads();
    }

    const int lr = lane >> 2, lc = lane & 3;
#pragma unroll
    for (int mt = 0; mt < 4; mt++) {
#pragma unroll
        for (int nt = 0; nt < 4; nt++) {
            int row = bm + wm * 64 + mt * 16 + lr;
            int col = bn + wn * 32 + nt * 8 + lc * 2;
            float b0 = __ldg(bias + col), b1 = __ldg(bias + col + 1);
            float2 v0 = make_float2(acc[mt][nt][0] + b0, acc[mt][nt][1] + b1);
            float2 v1 = make_float2(acc[mt][nt][2] + b0, acc[mt][nt][3] + b1);
            if (round_out) {
                v0.x = __uint_as_float(f2tf32(v0.x));
                v0.y = __uint_as_float(f2tf32(v0.y));
                v1.x = __uint_as_float(f2tf32(v1.x));
                v1.y = __uint_as_float(f2tf32(v1.y));
            }
            if (split) {
                int h_ = col >> 6, d_ = col & 63;
                int b_ = row >> 11, t_ = row & 2047;
                size_t base = (((size_t)(b_ * Hx + h_) * Tx) + t_) * Dx + d_;
                *(float2*)(out + base) = v0;
                int t2 = (row + 8) & 2047;
                size_t base2 = (((size_t)(b_ * Hx + h_) * Tx) + t2) * Dx + d_;
                *(float2*)(out + base2) = v1;
            } else {
                *(float2*)(out + (size_t)row * Cx + col) = v0;
                *(float2*)(out + (size_t)(row + 8) * Cx + col) = v1;
            }
        }
    }
}

// ---------------------------------------------------------------------------
// Tensor-core flash attention (tf32 mma.sync), no P smem (shuffle transpose).
// CTA = 128 q-rows, 8 warps x 16 rows. K-tiles of 128, processed in 64-key
// chunks. Inputs already tf32-rounded (raw-copy fills). 2 CTAs/SM.
// ---------------------------------------------------------------------------
__global__ __launch_bounds__(256, 2) void attn_mma(
    const float* __restrict__ q, const float* __restrict__ k,
    const float* __restrict__ v, float* __restrict__ y)
{
    constexpr int QP = 68, KP = 68, VP = 72;
    extern __shared__ uint32_t sw[];
    uint32_t* Qs = sw;                 // 128*QP
    uint32_t* Ks = Qs + 128 * QP;      // 128*KP
    uint32_t* Vs = Ks + 128 * KP;      // 128*VP   -> 106496 bytes total

    const int bh = blockIdx.y;
    const int qt = gridDim.x - 1 - blockIdx.x;   // heaviest tiles first
    const int q0 = qt * 128;
    const int tid = threadIdx.x;
    const int wid = tid >> 5, lane = tid & 31;
    const int lr = lane >> 2, lc = lane & 3;
    const float* qb = q + (size_t)bh * Tx * Dx;
    const float* kb = k + (size_t)bh * Tx * Dx;
    const float* vb = v + (size_t)bh * Tx * Dx;

    // Load Q tile: raw copy with 1/8 scale folded (exact on tf32 values)
#pragma unroll
    for (int l = 0; l < 8; l++) {
        int f = tid + l * 256;
        int r = f >> 4, c4 = (f & 15) * 4;
        float4 t = *(const float4*)&qb[(size_t)(q0 + r) * Dx + c4];
        t.x *= 0.125f; t.y *= 0.125f; t.z *= 0.125f; t.w *= 0.125f;
        *(float4*)&Qs[r * QP + c4] = t;
    }

    float m0 = -1e30f, m1 = -1e30f, l0 = 0.0f, l1 = 0.0f;
    float o[8][4];
#pragma unroll
    for (int dn = 0; dn < 8; dn++)
#pragma unroll
        for (int r = 0; r < 4; r++) o[dn][r] = 0.0f;

    const uint32_t srcA = (lane & ~3) | (lc >> 1);
    const uint32_t srcB = srcA + 2;

    for (int jb = 0; jb <= qt; jb++) {
        const int j0 = jb * 128;
        __syncthreads();               // prior iter done reading Ks/Vs
#pragma unroll
        for (int l = 0; l < 8; l++) {
            int f = tid + l * 256;
            int r = f >> 4, c4 = (f & 15) * 4;
            *(float4*)&Ks[r * KP + c4] = *(const float4*)&kb[(size_t)(j0 + r) * Dx + c4];
            *(float4*)&Vs[r * VP + c4] = *(const float4*)&vb[(size_t)(j0 + r) * Dx + c4];
        }
        __syncthreads();

#pragma unroll
        for (int cc = 0; cc < 2; cc++) {
            // On the diagonal tile, warps 0-3 (rows < 64) see chunk 1 fully masked
            if (jb == qt && cc == 1 && wid < 4) continue;
            const int kb0 = cc * 64;

            // S = Q @ K^T for this 64-key chunk (8 n-tiles)
            float s[8][4];
#pragma unroll
            for (int nt = 0; nt < 8; nt++)
#pragma unroll
                for (int r = 0; r < 4; r++) s[nt][r] = 0.0f;

#pragma unroll
            for (int ks = 0; ks < 8; ks++) {
                uint32_t a0 = Qs[(wid * 16 + lr) * QP + ks * 8 + lc];
                uint32_t a1 = Qs[(wid * 16 + lr + 8) * QP + ks * 8 + lc];
                uint32_t a2 = Qs[(wid * 16 + lr) * QP + ks * 8 + lc + 4];
                uint32_t a3 = Qs[(wid * 16 + lr + 8) * QP + ks * 8 + lc + 4];
#pragma unroll
                for (int nt = 0; nt < 8; nt++) {
                    uint32_t b0 = Ks[(kb0 + nt * 8 + lr) * KP + ks * 8 + lc];
                    uint32_t b1 = Ks[(kb0 + nt * 8 + lr) * KP + ks * 8 + lc + 4];
                    MMA_TF32(s[nt], a0, a1, a2, a3, b0, b1);
                }
            }

            // Causal mask (diagonal tile only)
            if (jb == qt) {
                int r0g = q0 + wid * 16 + lr;
                int r1g = r0g + 8;
#pragma unroll
                for (int nt = 0; nt < 8; nt++) {
                    int c0g = j0 + kb0 + nt * 8 + lc * 2;
                    if (c0g > r0g)     s[nt][0] = -1e30f;
                    if (c0g + 1 > r0g) s[nt][1] = -1e30f;
                    if (c0g > r1g)     s[nt][2] = -1e30f;
                    if (c0g + 1 > r1g) s[nt][3] = -1e30f;
                }
            }

            // Online softmax for the chunk
            float tm0 = -1e30f, tm1 = -1e30f;
#pragma unroll
            for (int nt = 0; nt < 8; nt++) {
                tm0 = fmaxf(tm0, fmaxf(s[nt][0], s[nt][1]));
                tm1 = fmaxf(tm1, fmaxf(s[nt][2], s[nt][3]));
            }
            tm0 = fmaxf(tm0, __shfl_xor_sync(0xffffffffu, tm0, 1));
            tm0 = fmaxf(tm0, __shfl_xor_sync(0xffffffffu, tm0, 2));
            tm1 = fmaxf(tm1, __shfl_xor_sync(0xffffffffu, tm1, 1));
            tm1 = fmaxf(tm1, __shfl_xor_sync(0xffffffffu, tm1, 2));

            float mn0 = fmaxf(m0, tm0), mn1 = fmaxf(m1, tm1);
            float f0 = __expf(m0 - mn0), f1 = __expf(m1 - mn1);
            float su0 = 0.0f, su1 = 0.0f;
#pragma unroll
            for (int nt = 0; nt < 8; nt++) {
                float p0 = __expf(s[nt][0] - mn0);
                float p1 = __expf(s[nt][1] - mn0);
                float p2 = __expf(s[nt][2] - mn1);
                float p3 = __expf(s[nt][3] - mn1);
                su0 += p0 + p1;
                su1 += p2 + p3;
                s[nt][0] = __uint_as_float(f2tf32(p0));
                s[nt][1] = __uint_as_float(f2tf32(p1));
                s[nt][2] = __uint_as_float(f2tf32(p2));
                s[nt][3] = __uint_as_float(f2tf32(p3));
            }
            su0 += __shfl_xor_sync(0xffffffffu, su0, 1);
            su0 += __shfl_xor_sync(0xffffffffu, su0, 2);
            su1 += __shfl_xor_sync(0xffffffffu, su1, 1);
            su1 += __shfl_xor_sync(0xffffffffu, su1, 2);

            l0 = l0 * f0 + su0;
            l1 = l1 * f1 + su1;
            m0 = mn0; m1 = mn1;
#pragma unroll
            for (int dn = 0; dn < 8; dn++) {
                o[dn][0] *= f0; o[dn][1] *= f0;
                o[dn][2] *= f1; o[dn][3] *= f1;
            }

            // O += P @ V : shuffle-transpose S accum -> A fragments (per quad)
#pragma unroll
            for (int nt = 0; nt < 8; nt++) {
                float u0 = __shfl_sync(0xffffffffu, s[nt][0], srcA);
                float u1 = __shfl_sync(0xffffffffu, s[nt][1], srcA);
                float u2 = __shfl_sync(0xffffffffu, s[nt][2], srcA);
                float u3 = __shfl_sync(0xffffffffu, s[nt][3], srcA);
                float w0 = __shfl_sync(0xffffffffu, s[nt][0], srcB);
                float w1 = __shfl_sync(0xffffffffu, s[nt][1], srcB);
                float w2 = __shfl_sync(0xffffffffu, s[nt][2], srcB);
                float w3 = __shfl_sync(0xffffffffu, s[nt][3], srcB);
                bool odd = (lc & 1);
                uint32_t a0 = __float_as_uint(odd ? u1 : u0);
                uint32_t a1 = __float_as_uint(odd ? u3 : u2);
                uint32_t a2 = __float_as_uint(odd ? w1 : w0);
                uint32_t a3 = __float_as_uint(odd ? w3 : w2);
                const int kr = kb0 + nt * 8;
#pragma unroll
                for (int dn = 0; dn < 8; dn++) {
                    uint32_t b0 = Vs[(kr + lc) * VP + dn * 8 + lr];
                    uint32_t b1 = Vs[(kr + lc + 4) * VP + dn * 8 + lr];
                    MMA_TF32(o[dn], a0, a1, a2, a3, b0, b1);
                }
            }
        }
    }

    // Epilogue: y[B,T,C], rounded to tf32 for the final GEMM
    const int b_ = bh >> 4, h_ = bh & 15;
    const float i0 = 1.0f / l0, i1 = 1.0f / l1;
    const int r0g = q0 + wid * 16 + lr;
#pragma unroll
    for (int dn = 0; dn < 8; dn++) {
        int col = h_ * Dx + dn * 8 + lc * 2;
        float2 w0, w1;
        w0.x = __uint_as_float(f2tf32(o[dn][0] * i0));
        w0.y = __uint_as_float(f2tf32(o[dn][1] * i0));
        w1.x = __uint_as_float(f2tf32(o[dn][2] * i1));
        w1.y = __uint_as_float(f2tf32(o[dn][3] * i1));
        *(float2*)&y[((size_t)b_ * Tx + r0g) * Cx + col] = w0;
        *(float2*)&y[((size_t)b_ * Tx + r0g + 8) * Cx + col] = w1;
    }
}

// ---------------------------------------------------------------------------
extern "C" void kernel_launch(void* const* d_in, const int* in_sizes, int n_in,
                              void* d_out, int out_size)
{
    const float* x  = (const float*)d_in[0];
    // d_in[1] = att_mask (causal tril) — handled structurally in-kernel
    const float* wq = (const float*)d_in[2];
    const float* bq = (const float*)d_in[3];
    const float* wk = (const float*)d_in[4];
    const float* bk = (const float*)d_in[5];
    const float* wv = (const float*)d_in[6];
    const float* bv = (const float*)d_in[7];
    const float* wp = (const float*)d_in[8];
    const float* bp = (const float*)d_in[9];
    float* out = (float*)d_out;

    float *qp, *kp, *vp, *yp, *xr;
    cudaGetSymbolAddress((void**)&qp, g_q);
    cudaGetSymbolAddress((void**)&kp, g_k);
    cudaGetSymbolAddress((void**)&vp, g_v);
    cudaGetSymbolAddress((void**)&yp, g_y);
    cudaGetSymbolAddress((void**)&xr, g_xr);

    const int gemm_smem = 3 * 36864;   // 110592 (3 stages)
    cudaFuncSetAttribute(mma_gemm, cudaFuncAttributeMaxDynamicSharedMemorySize, gemm_smem);
    dim3 gg(Cx / 128, Mrows / 128);    // (8, 32)

    // Pre-round X once; QKV GEMMs skip A-cvt and emit tf32-rounded outputs
    round_tf32_kernel<<<Mrows * Cx / 1024, 256>>>(x, xr, Mrows * Cx);

    mma_gemm<<<gg, 256, gemm_smem>>>(xr, wq, bq, qp, 1, 1, 1);
    mma_gemm<<<gg, 256, gemm_smem>>>(xr, wk, bk, kp, 1, 1, 1);
    mma_gemm<<<gg, 256, gemm_smem>>>(xr, wv, bv, vp, 1, 1, 1);

    const int attn_smem = 128 * (68 + 68 + 72) * 4;   // 106496
    cudaFuncSetAttribute(attn_mma, cudaFuncAttributeMaxDynamicSharedMemorySize, attn_smem);
    attn_mma<<<dim3(Tx / 128, Bx * Hx), 256, attn_smem>>>(qp, kp, vp, yp);

    // y is tf32-rounded by attn epilogue
    mma_gemm<<<gg, 256, gemm_smem>>>(yp, wp, bp, out, 0, 1, 0);
}

// round 10
// speedup vs baseline: 4.5714x; 1.0667x over previous
#include <cuda_runtime.h>
#include <cstdint>

// Problem constants
#define Bx 2
#define Tx 2048
#define Cx 1024
#define Hx 16
#define Dx 64
#define Mrows (Bx*Tx)   // 4096

// Scratch in __device__ globals (no allocations allowed)
__device__ float g_q[(size_t)Bx*Hx*Tx*Dx];    // [B,H,T,D] (tf32-rounded)
__device__ float g_k[(size_t)Bx*Hx*Tx*Dx];
__device__ float g_v[(size_t)Bx*Hx*Tx*Dx];
__device__ float g_y[(size_t)Mrows*Cx];       // [B*T, C]  (tf32-rounded)
__device__ float g_xr[(size_t)Mrows*Cx];      // tf32-rounded X
__device__ float g_wr4[4][(size_t)Cx*Cx];     // tf32-rounded Wq,Wk,Wv,Wp

__device__ __forceinline__ uint32_t smem_u32(const void* p) {
    uint32_t a;
    asm("{ .reg .u64 t; cvta.to.shared.u64 t, %1; cvt.u32.u64 %0, t; }" : "=r"(a) : "l"(p));
    return a;
}
__device__ __forceinline__ uint32_t f2tf32(float f) {
    uint32_t u;
    asm("cvt.rna.tf32.f32 %0, %1;" : "=r"(u) : "f"(f));
    return u;
}
__device__ __forceinline__ void ldsm_x4(uint32_t* r, uint32_t addr) {
    asm volatile("ldmatrix.sync.aligned.m8n8.x4.shared.b16 {%0,%1,%2,%3}, [%4];"
        : "=r"(r[0]), "=r"(r[1]), "=r"(r[2]), "=r"(r[3]) : "r"(addr));
}
__device__ __forceinline__ void ldsm_x2(uint32_t* r, uint32_t addr) {
    asm volatile("ldmatrix.sync.aligned.m8n8.x2.shared.b16 {%0,%1}, [%2];"
        : "=r"(r[0]), "=r"(r[1]) : "r"(addr));
}
#define MMA_TF32(C, A0,A1,A2,A3, B0,B1) \
    asm volatile("mma.sync.aligned.m16n8k8.row.col.f32.tf32.tf32.f32 " \
        "{%0,%1,%2,%3}, {%4,%5,%6,%7}, {%8,%9}, {%0,%1,%2,%3};" \
        : "+f"((C)[0]), "+f"((C)[1]), "+f"((C)[2]), "+f"((C)[3]) \
        : "r"(A0), "r"(A1), "r"(A2), "r"(A3), "r"(B0), "r"(B1))

// ---------------------------------------------------------------------------
// Fused tf32 rounding pre-pass: X (4M elems) + 4 weights (1M each).
// grid.x = 4096 + 4*1024 blocks, 1024 elems/block.
// ---------------------------------------------------------------------------
__global__ __launch_bounds__(256) void round_all_kernel(
    const float* __restrict__ x,
    const float* __restrict__ wq, const float* __restrict__ wk,
    const float* __restrict__ wv, const float* __restrict__ wp,
    float* __restrict__ xr, float* __restrict__ wr)
{
    int bid = blockIdx.x;
    const float* src;
    float* dst;
    int off;
    if (bid < 4096) {
        src = x; dst = xr; off = bid * 1024;
    } else {
        int seg = (bid - 4096) >> 10;
        off = ((bid - 4096) & 1023) * 1024;
        src = (seg == 0) ? wq : (seg == 1) ? wk : (seg == 2) ? wv : wp;
        dst = wr + (size_t)seg * Cx * Cx;
    }
    int i = off + threadIdx.x * 4;
    float4 v = *(const float4*)(src + i);
    float4 o;
    o.x = __uint_as_float(f2tf32(v.x));
    o.y = __uint_as_float(f2tf32(v.y));
    o.z = __uint_as_float(f2tf32(v.z));
    o.w = __uint_as_float(f2tf32(v.w));
    *(float4*)(dst + i) = o;
}

// ---------------------------------------------------------------------------
// tf32 mma.sync GEMM (all inputs pre-rounded to tf32; ldmatrix fragments).
// out[4096,1024] = X @ W^T + bias. CTA 128x128, BK=32, 8 warps (2x4) x 64x32.
// 3-stage cp.async. grid.z selects (W, bias, out) set for fused QKV.
// ---------------------------------------------------------------------------
__global__ __launch_bounds__(256, 2) void mma_gemm(
    const float* __restrict__ X,
    const float* __restrict__ Wa, const float* __restrict__ Wb2,
    const float* __restrict__ Wc,
    const float* __restrict__ ba, const float* __restrict__ bb2,
    const float* __restrict__ bc,
    float* __restrict__ oa, float* __restrict__ ob2, float* __restrict__ oc,
    int split, int round_out)
{
    constexpr int NK = 32;
    constexpr uint32_t LDB = 144u;     // 36 floats row stride (bytes)
    constexpr uint32_t STB = 36864u;   // per stage: A 18432 + B 18432
    extern __shared__ float smf[];
    const uint32_t sb = smem_u32(smf);

    const int z = blockIdx.z;
    const float* W    = (z == 0) ? Wa : (z == 1) ? Wb2 : Wc;
    const float* bias = (z == 0) ? ba : (z == 1) ? bb2 : bc;
    float* out        = (z == 0) ? oa : (z == 1) ? ob2 : oc;

    const int tid = threadIdx.x;
    const int wid = tid >> 5, lane = tid & 31;
    const int wm = wid >> 2, wn = wid & 3;
    const int bm = blockIdx.y * 128, bn = blockIdx.x * 128;

    const float* Xb = X + (size_t)bm * 1024;
    const float* Wb = W + (size_t)bn * 1024;

    // ldmatrix per-lane address offsets (bytes)
    const uint32_t aOff = (uint32_t)(lane & 15) * LDB + ((lane >> 4) & 1) * 16u;
    const uint32_t bOff = (uint32_t)(lane & 7) * LDB + ((lane >> 3) & 1) * 16u;

    float acc[4][4][4];
#pragma unroll
    for (int mt = 0; mt < 4; mt++)
#pragma unroll
        for (int nt = 0; nt < 4; nt++)
#pragma unroll
            for (int r = 0; r < 4; r++) acc[mt][nt][r] = 0.0f;

    auto load_stage = [&](int s, int kc) {
        uint32_t A = sb + (uint32_t)s * STB;
        uint32_t B = A + 18432u;
        const float* xs = Xb + kc * 32;
        const float* ws = Wb + kc * 32;
#pragma unroll
        for (int i = 0; i < 4; i++) {
            int f = tid + i * 256;
            int r = f >> 3;
            int c4 = (f & 7) * 4;
            uint32_t off = (uint32_t)r * LDB + (uint32_t)c4 * 4u;
            asm volatile("cp.async.cg.shared.global [%0], [%1], 16;"
                         :: "r"(A + off), "l"(xs + (size_t)r * 1024 + c4) : "memory");
            asm volatile("cp.async.cg.shared.global [%0], [%1], 16;"
                         :: "r"(B + off), "l"(ws + (size_t)r * 1024 + c4) : "memory");
        }
        asm volatile("cp.async.commit_group;" ::: "memory");
    };

    load_stage(0, 0);
    load_stage(1, 1);

    for (int k = 0; k < NK; k++) {
        if (k + 2 < NK) {
            load_stage((k + 2) % 3, k + 2);
            asm volatile("cp.async.wait_group 2;" ::: "memory");
        } else if (k + 1 < NK) {
            asm volatile("cp.async.wait_group 1;" ::: "memory");
        } else {
            asm volatile("cp.async.wait_group 0;" ::: "memory");
        }
        __syncthreads();

        const uint32_t As = sb + (uint32_t)(k % 3) * STB;
        const uint32_t Bs = As + 18432u;
        const uint32_t aBase = As + (uint32_t)(wm * 64) * LDB + aOff;
        const uint32_t bBase = Bs + (uint32_t)(wn * 32) * LDB + bOff;

#pragma unroll
        for (int kk = 0; kk < 4; kk++) {
            uint32_t af[4][4], bf[4][2];
#pragma unroll
            for (int mt = 0; mt < 4; mt++)
                ldsm_x4(af[mt], aBase + (uint32_t)(mt * 16) * LDB + kk * 32u);
#pragma unroll
            for (int nt = 0; nt < 4; nt++)
                ldsm_x2(bf[nt], bBase + (uint32_t)(nt * 8) * LDB + kk * 32u);
#pragma unroll
            for (int mt = 0; mt < 4; mt++)
#pragma unroll
                for (int nt = 0; nt < 4; nt++)
                    MMA_TF32(acc[mt][nt], af[mt][0], af[mt][1], af[mt][2], af[mt][3],
                             bf[nt][0], bf[nt][1]);
        }
        __syncthreads();
    }

    const int lr = lane >> 2, lc = lane & 3;
#pragma unroll
    for (int mt = 0; mt < 4; mt++) {
#pragma unroll
        for (int nt = 0; nt < 4; nt++) {
            int row = bm + wm * 64 + mt * 16 + lr;
            int col = bn + wn * 32 + nt * 8 + lc * 2;
            float b0 = __ldg(bias + col), b1 = __ldg(bias + col + 1);
            float2 v0 = make_float2(acc[mt][nt][0] + b0, acc[mt][nt][1] + b1);
            float2 v1 = make_float2(acc[mt][nt][2] + b0, acc[mt][nt][3] + b1);
            if (round_out) {
                v0.x = __uint_as_float(f2tf32(v0.x));
                v0.y = __uint_as_float(f2tf32(v0.y));
                v1.x = __uint_as_float(f2tf32(v1.x));
                v1.y = __uint_as_float(f2tf32(v1.y));
            }
            if (split) {
                int h_ = col >> 6, d_ = col & 63;
                int b_ = row >> 11, t_ = row & 2047;
                size_t base = (((size_t)(b_ * Hx + h_) * Tx) + t_) * Dx + d_;
                *(float2*)(out + base) = v0;
                int t2 = (row + 8) & 2047;
                size_t base2 = (((size_t)(b_ * Hx + h_) * Tx) + t2) * Dx + d_;
                *(float2*)(out + base2) = v1;
            } else {
                *(float2*)(out + (size_t)row * Cx + col) = v0;
                *(float2*)(out + (size_t)(row + 8) * Cx + col) = v1;
            }
        }
    }
}

// ---------------------------------------------------------------------------
// Tensor-core flash attention (tf32 mma.sync), ldmatrix Q/K frags,
// shuffle-transpose P (no P smem). CTA = 128 q-rows, 8 warps x 16 rows.
// K-tiles of 128 in 64-key chunks. Inputs pre-rounded. 2 CTAs/SM.
// ---------------------------------------------------------------------------
__global__ __launch_bounds__(256, 2) void attn_mma(
    const float* __restrict__ q, const float* __restrict__ k,
    const float* __restrict__ v, float* __restrict__ y)
{
    constexpr int QP = 68, KP = 68, VP = 72;
    constexpr uint32_t QPB = QP * 4, KPB = KP * 4;
    extern __shared__ uint32_t sw[];
    uint32_t* Qs = sw;                 // 128*QP
    uint32_t* Ks = Qs + 128 * QP;      // 128*KP
    uint32_t* Vs = Ks + 128 * KP;      // 128*VP  -> 106496 bytes total

    const int bh = blockIdx.y;
    const int qt = gridDim.x - 1 - blockIdx.x;   // heaviest tiles first
    const int q0 = qt * 128;
    const int tid = threadIdx.x;
    const int wid = tid >> 5, lane = tid & 31;
    const int lr = lane >> 2, lc = lane & 3;
    const float* qb = q + (size_t)bh * Tx * Dx;
    const float* kb = k + (size_t)bh * Tx * Dx;
    const float* vb = v + (size_t)bh * Tx * Dx;

    const uint32_t sQ = smem_u32(Qs), sK = smem_u32(Ks);
    const uint32_t qOff = (uint32_t)(lane & 15) * QPB + ((lane >> 4) & 1) * 16u
                        + (uint32_t)(wid * 16) * QPB;
    const uint32_t kOff = (uint32_t)(lane & 7) * KPB + ((lane >> 3) & 1) * 16u;

    // Load Q tile: raw copy with 1/8 scale folded (exact on tf32 values)
#pragma unroll
    for (int l = 0; l < 8; l++) {
        int f = tid + l * 256;
        int r = f >> 4, c4 = (f & 15) * 4;
        float4 t = *(const float4*)&qb[(size_t)(q0 + r) * Dx + c4];
        t.x *= 0.125f; t.y *= 0.125f; t.z *= 0.125f; t.w *= 0.125f;
        *(float4*)&Qs[r * QP + c4] = t;
    }

    float m0 = -1e30f, m1 = -1e30f, l0 = 0.0f, l1 = 0.0f;
    float o[8][4];
#pragma unroll
    for (int dn = 0; dn < 8; dn++)
#pragma unroll
        for (int r = 0; r < 4; r++) o[dn][r] = 0.0f;

    const uint32_t srcA = (lane & ~3) | (lc >> 1);
    const uint32_t srcB = srcA + 2;

    for (int jb = 0; jb <= qt; jb++) {
        const int j0 = jb * 128;
        __syncthreads();               // prior iter done reading Ks/Vs
#pragma unroll
        for (int l = 0; l < 8; l++) {
            int f = tid + l * 256;
            int r = f >> 4, c4 = (f & 15) * 4;
            *(float4*)&Ks[r * KP + c4] = *(const float4*)&kb[(size_t)(j0 + r) * Dx + c4];
            *(float4*)&Vs[r * VP + c4] = *(const float4*)&vb[(size_t)(j0 + r) * Dx + c4];
        }
        __syncthreads();

#pragma unroll
        for (int cc = 0; cc < 2; cc++) {
            // On the diagonal tile, warps 0-3 (rows < 64) see chunk 1 fully masked
            if (jb == qt && cc == 1 && wid < 4) continue;
            const int kb0 = cc * 64;

            // S = Q @ K^T for this 64-key chunk (8 n-tiles)
            float s[8][4];
#pragma unroll
            for (int nt = 0; nt < 8; nt++)
#pragma unroll
                for (int r = 0; r < 4; r++) s[nt][r] = 0.0f;

#pragma unroll
            for (int ks = 0; ks < 8; ks++) {
                uint32_t af[4];
                ldsm_x4(af, sQ + qOff + ks * 32u);
#pragma unroll
                for (int nt = 0; nt < 8; nt++) {
                    uint32_t bf[2];
                    ldsm_x2(bf, sK + (uint32_t)((kb0 + nt * 8)) * KPB + kOff + ks * 32u);
                    MMA_TF32(s[nt], af[0], af[1], af[2], af[3], bf[0], bf[1]);
                }
            }

            // Causal mask (diagonal tile only)
            if (jb == qt) {
                int r0g = q0 + wid * 16 + lr;
                int r1g = r0g + 8;
#pragma unroll
                for (int nt = 0; nt < 8; nt++) {
                    int c0g = j0 + kb0 + nt * 8 + lc * 2;
                    if (c0g > r0g)     s[nt][0] = -1e30f;
                    if (c0g + 1 > r0g) s[nt][1] = -1e30f;
                    if (c0g > r1g)     s[nt][2] = -1e30f;
                    if (c0g + 1 > r1g) s[nt][3] = -1e30f;
                }
            }

            // Online softmax for the chunk
            float tm0 = -1e30f, tm1 = -1e30f;
#pragma unroll
            for (int nt = 0; nt < 8; nt++) {
                tm0 = fmaxf(tm0, fmaxf(s[nt][0], s[nt][1]));
                tm1 = fmaxf(tm1, fmaxf(s[nt][2], s[nt][3]));
            }
            tm0 = fmaxf(tm0, __shfl_xor_sync(0xffffffffu, tm0, 1));
            tm0 = fmaxf(tm0, __shfl_xor_sync(0xffffffffu, tm0, 2));
            tm1 = fmaxf(tm1, __shfl_xor_sync(0xffffffffu, tm1, 1));
            tm1 = fmaxf(tm1, __shfl_xor_sync(0xffffffffu, tm1, 2));

            float mn0 = fmaxf(m0, tm0), mn1 = fmaxf(m1, tm1);
            float f0 = __expf(m0 - mn0), f1 = __expf(m1 - mn1);
            float su0 = 0.0f, su1 = 0.0f;
#pragma unroll
            for (int nt = 0; nt < 8; nt++) {
                float p0 = __expf(s[nt][0] - mn0);
                float p1 = __expf(s[nt][1] - mn0);
                float p2 = __expf(s[nt][2] - mn1);
                float p3 = __expf(s[nt][3] - mn1);
                su0 += p0 + p1;
                su1 += p2 + p3;
                s[nt][0] = __uint_as_float(f2tf32(p0));
                s[nt][1] = __uint_as_float(f2tf32(p1));
                s[nt][2] = __uint_as_float(f2tf32(p2));
                s[nt][3] = __uint_as_float(f2tf32(p3));
            }
            su0 += __shfl_xor_sync(0xffffffffu, su0, 1);
            su0 += __shfl_xor_sync(0xffffffffu, su0, 2);
            su1 += __shfl_xor_sync(0xffffffffu, su1, 1);
            su1 += __shfl_xor_sync(0xffffffffu, su1, 2);

            l0 = l0 * f0 + su0;
            l1 = l1 * f1 + su1;
            m0 = mn0; m1 = mn1;
#pragma unroll
            for (int dn = 0; dn < 8; dn++) {
                o[dn][0] *= f0; o[dn][1] *= f0;
                o[dn][2] *= f1; o[dn][3] *= f1;
            }

            // O += P @ V : shuffle-transpose S accum -> A fragments (per quad)
#pragma unroll
            for (int nt = 0; nt < 8; nt++) {
                float u0 = __shfl_sync(0xffffffffu, s[nt][0], srcA);
                float u1 = __shfl_sync(0xffffffffu, s[nt][1], srcA);
                float u2 = __shfl_sync(0xffffffffu, s[nt][2], srcA);
                float u3 = __shfl_sync(0xffffffffu, s[nt][3], srcA);
                float w0 = __shfl_sync(0xffffffffu, s[nt][0], srcB);
                float w1 = __shfl_sync(0xffffffffu, s[nt][1], srcB);
                float w2 = __shfl_sync(0xffffffffu, s[nt][2], srcB);
                float w3 = __shfl_sync(0xffffffffu, s[nt][3], srcB);
                bool odd = (lc & 1);
                uint32_t a0 = __float_as_uint(odd ? u1 : u0);
                uint32_t a1 = __float_as_uint(odd ? u3 : u2);
                uint32_t a2 = __float_as_uint(odd ? w1 : w0);
                uint32_t a3 = __float_as_uint(odd ? w3 : w2);
                const int kr = kb0 + nt * 8;
#pragma unroll
                for (int dn = 0; dn < 8; dn++) {
                    uint32_t b0 = Vs[(kr + lc) * VP + dn * 8 + lr];
                    uint32_t b1 = Vs[(kr + lc + 4) * VP + dn * 8 + lr];
                    MMA_TF32(o[dn], a0, a1, a2, a3, b0, b1);
                }
            }
        }
    }

    // Epilogue: y[B,T,C], rounded to tf32 for the final GEMM
    const int b_ = bh >> 4, h_ = bh & 15;
    const float i0 = 1.0f / l0, i1 = 1.0f / l1;
    const int r0g = q0 + wid * 16 + lr;
#pragma unroll
    for (int dn = 0; dn < 8; dn++) {
        int col = h_ * Dx + dn * 8 + lc * 2;
        float2 w0, w1;
        w0.x = __uint_as_float(f2tf32(o[dn][0] * i0));
        w0.y = __uint_as_float(f2tf32(o[dn][1] * i0));
        w1.x = __uint_as_float(f2tf32(o[dn][2] * i1));
        w1.y = __uint_as_float(f2tf32(o[dn][3] * i1));
        *(float2*)&y[((size_t)b_ * Tx + r0g) * Cx + col] = w0;
        *(float2*)&y[((size_t)b_ * Tx + r0g + 8) * Cx + col] = w1;
    }
}

// ---------------------------------------------------------------------------
extern "C" void kernel_launch(void* const* d_in, const int* in_sizes, int n_in,
                              void* d_out, int out_size)
{
    const float* x  = (const float*)d_in[0];
    // d_in[1] = att_mask (causal tril) — handled structurally in-kernel
    const float* wq = (const float*)d_in[2];
    const float* bq = (const float*)d_in[3];
    const float* wk = (const float*)d_in[4];
    const float* bk = (const float*)d_in[5];
    const float* wv = (const float*)d_in[6];
    const float* bv = (const float*)d_in[7];
    const float* wp = (const float*)d_in[8];
    const float* bp = (const float*)d_in[9];
    float* out = (float*)d_out;

    float *qp, *kp, *vp, *yp, *xr, *wr;
    cudaGetSymbolAddress((void**)&qp, g_q);
    cudaGetSymbolAddress((void**)&kp, g_k);
    cudaGetSymbolAddress((void**)&vp, g_v);
    cudaGetSymbolAddress((void**)&yp, g_y);
    cudaGetSymbolAddress((void**)&xr, g_xr);
    cudaGetSymbolAddress((void**)&wr, g_wr4);

    const int gemm_smem = 3 * 36864;   // 110592 (3 stages)
    cudaFuncSetAttribute(mma_gemm, cudaFuncAttributeMaxDynamicSharedMemorySize, gemm_smem);

    // Pre-round X + all weights to tf32 (one launch)
    round_all_kernel<<<4096 + 4 * 1024, 256>>>(x, wq, wk, wv, wp, xr, wr);

    // Fused QKV projection: grid.z selects W/bias/out
    mma_gemm<<<dim3(8, 32, 3), 256, gemm_smem>>>(
        xr, wr, wr + (size_t)Cx * Cx, wr + 2 * (size_t)Cx * Cx,
        bq, bk, bv, qp, kp, vp, 1, 1);

    const int attn_smem = 128 * (68 + 68 + 72) * 4;   // 106496
    cudaFuncSetAttribute(attn_mma, cudaFuncAttributeMaxDynamicSharedMemorySize, attn_smem);
    attn_mma<<<dim3(Tx / 128, Bx * Hx), 256, attn_smem>>>(qp, kp, vp, yp);

    // Output projection (y tf32-rounded by attn epilogue)
    mma_gemm<<<dim3(8, 32, 1), 256, gemm_smem>>>(
        yp, wr + 3 * (size_t)Cx * Cx, nullptr, nullptr,
        bp, nullptr, nullptr, out, nullptr, nullptr, 0, 0);
}

// round 13
// speedup vs baseline: 4.7769x; 1.0449x over previous
#include <cuda_runtime.h>
#include <cstdint>

// Problem constants
#define Bx 2
#define Tx 2048
#define Cx 1024
#define Hx 16
#define Dx 64
#define Mrows (Bx*Tx)   // 4096

// Scratch in __device__ globals (no allocations allowed)
__device__ float g_q[(size_t)Bx*Hx*Tx*Dx];    // [B,H,T,D] (tf32-rounded)
__device__ float g_k[(size_t)Bx*Hx*Tx*Dx];
__device__ float g_v[(size_t)Bx*Hx*Tx*Dx];
__device__ float g_y[(size_t)Mrows*Cx];       // [B*T, C]  (tf32-rounded)
__device__ float g_xr[(size_t)Mrows*Cx];      // tf32-rounded X
__device__ float g_wr4[4][(size_t)Cx*Cx];     // tf32-rounded Wq,Wk,Wv,Wp

__device__ __forceinline__ uint32_t smem_u32(const void* p) {
    uint32_t a;
    asm("{ .reg .u64 t; cvta.to.shared.u64 t, %1; cvt.u32.u64 %0, t; }" : "=r"(a) : "l"(p));
    return a;
}
__device__ __forceinline__ uint32_t f2tf32(float f) {
    uint32_t u;
    asm("cvt.rna.tf32.f32 %0, %1;" : "=r"(u) : "f"(f));
    return u;
}
__device__ __forceinline__ void ldsm_x4(uint32_t* r, uint32_t addr) {
    asm volatile("ldmatrix.sync.aligned.m8n8.x4.shared.b16 {%0,%1,%2,%3}, [%4];"
        : "=r"(r[0]), "=r"(r[1]), "=r"(r[2]), "=r"(r[3]) : "r"(addr));
}
__device__ __forceinline__ void ldsm_x2(uint32_t* r, uint32_t addr) {
    asm volatile("ldmatrix.sync.aligned.m8n8.x2.shared.b16 {%0,%1}, [%2];"
        : "=r"(r[0]), "=r"(r[1]) : "r"(addr));
}
#define MMA_TF32(C, A0,A1,A2,A3, B0,B1) \
    asm volatile("mma.sync.aligned.m16n8k8.row.col.f32.tf32.tf32.f32 " \
        "{%0,%1,%2,%3}, {%4,%5,%6,%7}, {%8,%9}, {%0,%1,%2,%3};" \
        : "+f"((C)[0]), "+f"((C)[1]), "+f"((C)[2]), "+f"((C)[3]) \
        : "r"(A0), "r"(A1), "r"(A2), "r"(A3), "r"(B0), "r"(B1))

// ---------------------------------------------------------------------------
// Fused tf32 rounding pre-pass: X (4M elems) + 4 weights (1M each).
// ---------------------------------------------------------------------------
__global__ __launch_bounds__(256) void round_all_kernel(
    const float* __restrict__ x,
    const float* __restrict__ wq, const float* __restrict__ wk,
    const float* __restrict__ wv, const float* __restrict__ wp,
    float* __restrict__ xr, float* __restrict__ wr)
{
    int bid = blockIdx.x;
    const float* src;
    float* dst;
    int off;
    if (bid < 4096) {
        src = x; dst = xr; off = bid * 1024;
    } else {
        int seg = (bid - 4096) >> 10;
        off = ((bid - 4096) & 1023) * 1024;
        src = (seg == 0) ? wq : (seg == 1) ? wk : (seg == 2) ? wv : wp;
        dst = wr + (size_t)seg * Cx * Cx;
    }
    int i = off + threadIdx.x * 4;
    float4 v = *(const float4*)(src + i);
    float4 o;
    o.x = __uint_as_float(f2tf32(v.x));
    o.y = __uint_as_float(f2tf32(v.y));
    o.z = __uint_as_float(f2tf32(v.z));
    o.w = __uint_as_float(f2tf32(v.w));
    *(float4*)(dst + i) = o;
}

// ---------------------------------------------------------------------------
// tf32 mma.sync GEMM (inputs pre-rounded; ldmatrix frags; 1 barrier/k-iter).
// out[4096,1024] = X @ W^T + bias. CTA 128x128, BK=32, 8 warps (2x4) x 64x32.
// 3-stage cp.async. grid.z selects (W, bias, out) set for fused QKV.
// ---------------------------------------------------------------------------
__global__ __launch_bounds__(256, 2) void mma_gemm(
    const float* __restrict__ X,
    const float* __restrict__ Wa, const float* __restrict__ Wb2,
    const float* __restrict__ Wc,
    const float* __restrict__ ba, const float* __restrict__ bb2,
    const float* __restrict__ bc,
    float* __restrict__ oa, float* __restrict__ ob2, float* __restrict__ oc,
    int split, int round_out)
{
    constexpr int NK = 32;
    constexpr uint32_t LDB = 144u;     // 36 floats row stride (bytes)
    constexpr uint32_t STB = 36864u;   // per stage: A 18432 + B 18432
    extern __shared__ float smf[];
    const uint32_t sb = smem_u32(smf);

    const int z = blockIdx.z;
    const float* W    = (z == 0) ? Wa : (z == 1) ? Wb2 : Wc;
    const float* bias = (z == 0) ? ba : (z == 1) ? bb2 : bc;
    float* out        = (z == 0) ? oa : (z == 1) ? ob2 : oc;

    const int tid = threadIdx.x;
    const int wid = tid >> 5, lane = tid & 31;
    const int wm = wid >> 2, wn = wid & 3;
    const int bm = blockIdx.y * 128, bn = blockIdx.x * 128;

    const float* Xb = X + (size_t)bm * 1024;
    const float* Wb = W + (size_t)bn * 1024;

    const uint32_t aOff = (uint32_t)(lane & 15) * LDB + ((lane >> 4) & 1) * 16u;
    const uint32_t bOff = (uint32_t)(lane & 7) * LDB + ((lane >> 3) & 1) * 16u;

    float acc[4][4][4];
#pragma unroll
    for (int mt = 0; mt < 4; mt++)
#pragma unroll
        for (int nt = 0; nt < 4; nt++)
#pragma unroll
            for (int r = 0; r < 4; r++) acc[mt][nt][r] = 0.0f;

    auto load_stage = [&](int s, int kc) {
        uint32_t A = sb + (uint32_t)s * STB;
        uint32_t B = A + 18432u;
        const float* xs = Xb + kc * 32;
        const float* ws = Wb + kc * 32;
#pragma unroll
        for (int i = 0; i < 4; i++) {
            int f = tid + i * 256;
            int r = f >> 3;
            int c4 = (f & 7) * 4;
            uint32_t off = (uint32_t)r * LDB + (uint32_t)c4 * 4u;
            asm volatile("cp.async.cg.shared.global [%0], [%1], 16;"
                         :: "r"(A + off), "l"(xs + (size_t)r * 1024 + c4) : "memory");
            asm volatile("cp.async.cg.shared.global [%0], [%1], 16;"
                         :: "r"(B + off), "l"(ws + (size_t)r * 1024 + c4) : "memory");
        }
        asm volatile("cp.async.commit_group;" ::: "memory");
    };

    load_stage(0, 0);
    load_stage(1, 1);

    for (int k = 0; k < NK; k++) {
        if (k + 1 < NK)
            asm volatile("cp.async.wait_group 1;" ::: "memory");
        else
            asm volatile("cp.async.wait_group 0;" ::: "memory");
        __syncthreads();
        // Safe: slot (k+2)%3 == (k-1)%3; its readers (iter k-1) are past this barrier.
        if (k + 2 < NK) load_stage((k + 2) % 3, k + 2);

        const uint32_t As = sb + (uint32_t)(k % 3) * STB;
        const uint32_t Bs = As + 18432u;
        const uint32_t aBase = As + (uint32_t)(wm * 64) * LDB + aOff;
        const uint32_t bBase = Bs + (uint32_t)(wn * 32) * LDB + bOff;

#pragma unroll
        for (int kk = 0; kk < 4; kk++) {
            uint32_t af[4][4], bf[4][2];
#pragma unroll
            for (int mt = 0; mt < 4; mt++)
                ldsm_x4(af[mt], aBase + (uint32_t)(mt * 16) * LDB + kk * 32u);
#pragma unroll
            for (int nt = 0; nt < 4; nt++)
                ldsm_x2(bf[nt], bBase + (uint32_t)(nt * 8) * LDB + kk * 32u);
#pragma unroll
            for (int mt = 0; mt < 4; mt++)
#pragma unroll
                for (int nt = 0; nt < 4; nt++)
                    MMA_TF32(acc[mt][nt], af[mt][0], af[mt][1], af[mt][2], af[mt][3],
                             bf[nt][0], bf[nt][1]);
        }
        // no trailing barrier: next overwrite of this slot is gated by the
        // top-of-iteration barrier two iterations ahead.
    }

    const int lr = lane >> 2, lc = lane & 3;
#pragma unroll
    for (int mt = 0; mt < 4; mt++) {
#pragma unroll
        for (int nt = 0; nt < 4; nt++) {
            int row = bm + wm * 64 + mt * 16 + lr;
            int col = bn + wn * 32 + nt * 8 + lc * 2;
            float b0 = __ldg(bias + col), b1 = __ldg(bias + col + 1);
            float2 v0 = make_float2(acc[mt][nt][0] + b0, acc[mt][nt][1] + b1);
            float2 v1 = make_float2(acc[mt][nt][2] + b0, acc[mt][nt][3] + b1);
            if (round_out) {
                v0.x = __uint_as_float(f2tf32(v0.x));
                v0.y = __uint_as_float(f2tf32(v0.y));
                v1.x = __uint_as_float(f2tf32(v1.x));
                v1.y = __uint_as_float(f2tf32(v1.y));
            }
            if (split) {
                int h_ = col >> 6, d_ = col & 63;
                int b_ = row >> 11, t_ = row & 2047;
                size_t base = (((size_t)(b_ * Hx + h_) * Tx) + t_) * Dx + d_;
                *(float2*)(out + base) = v0;
                int t2 = (row + 8) & 2047;
                size_t base2 = (((size_t)(b_ * Hx + h_) * Tx) + t2) * Dx + d_;
                *(float2*)(out + base2) = v1;
            } else {
                *(float2*)(out + (size_t)row * Cx + col) = v0;
                *(float2*)(out + (size_t)(row + 8) * Cx + col) = v1;
            }
        }
    }
}

// ---------------------------------------------------------------------------
// Tensor-core flash attention (tf32 mma.sync), ldmatrix Q/K frags,
// cp.async K/V fills, shuffle-transpose P. CTA = 128 q-rows, 8 warps x 16.
// K-tiles of 128 in 64-key chunks. Inputs pre-rounded. 2 CTAs/SM.
// ---------------------------------------------------------------------------
__global__ __launch_bounds__(256, 2) void attn_mma(
    const float* __restrict__ q, const float* __restrict__ k,
    const float* __restrict__ v, float* __restrict__ y)
{
    constexpr int QP = 68, KP = 68, VP = 72;
    constexpr uint32_t QPB = QP * 4, KPB = KP * 4, VPB = VP * 4;
    extern __shared__ uint32_t sw[];
    uint32_t* Qs = sw;                 // 128*QP
    uint32_t* Ks = Qs + 128 * QP;      // 128*KP
    uint32_t* Vs = Ks + 128 * KP;      // 128*VP  -> 106496 bytes total

    const int bh = blockIdx.y;
    const int qt = gridDim.x - 1 - blockIdx.x;   // heaviest tiles first
    const int q0 = qt * 128;
    const int tid = threadIdx.x;
    const int wid = tid >> 5, lane = tid & 31;
    const int lr = lane >> 2, lc = lane & 3;
    const float* qb = q + (size_t)bh * Tx * Dx;
    const float* kb = k + (size_t)bh * Tx * Dx;
    const float* vb = v + (size_t)bh * Tx * Dx;

    const uint32_t sQ = smem_u32(Qs), sK = smem_u32(Ks), sV = smem_u32(Vs);
    const uint32_t qOff = (uint32_t)(lane & 15) * QPB + ((lane >> 4) & 1) * 16u
                        + (uint32_t)(wid * 16) * QPB;
    const uint32_t kOff = (uint32_t)(lane & 7) * KPB + ((lane >> 3) & 1) * 16u;

    // Load Q tile: raw copy with 1/8 scale folded (exact on tf32 values)
#pragma unroll
    for (int l = 0; l < 8; l++) {
        int f = tid + l * 256;
        int r = f >> 4, c4 = (f & 15) * 4;
        float4 t = *(const float4*)&qb[(size_t)(q0 + r) * Dx + c4];
        t.x *= 0.125f; t.y *= 0.125f; t.z *= 0.125f; t.w *= 0.125f;
        *(float4*)&Qs[r * QP + c4] = t;
    }

    float m0 = -1e30f, m1 = -1e30f, l0 = 0.0f, l1 = 0.0f;
    float o[8][4];
#pragma unroll
    for (int dn = 0; dn < 8; dn++)
#pragma unroll
        for (int r = 0; r < 4; r++) o[dn][r] = 0.0f;

    const uint32_t srcA = (lane & ~3) | (lc >> 1);
    const uint32_t srcB = srcA + 2;

    for (int jb = 0; jb <= qt; jb++) {
        const int j0 = jb * 128;
        __syncthreads();               // prior iter done reading Ks/Vs
        // K/V fills via cp.async (no register round-trip)
#pragma unroll
        for (int l = 0; l < 8; l++) {
            int f = tid + l * 256;
            int r = f >> 4;
            uint32_t cb = (uint32_t)(f & 15) * 16u;   // byte col
            const char* kg = (const char*)&kb[(size_t)(j0 + r) * Dx] + cb;
            const char* vg = (const char*)&vb[(size_t)(j0 + r) * Dx] + cb;
            asm volatile("cp.async.cg.shared.global [%0], [%1], 16;"
                         :: "r"(sK + (uint32_t)r * KPB + cb), "l"(kg) : "memory");
            asm volatile("cp.async.cg.shared.global [%0], [%1], 16;"
                         :: "r"(sV + (uint32_t)r * VPB + cb), "l"(vg) : "memory");
        }
        asm volatile("cp.async.commit_group;" ::: "memory");
        asm volatile("cp.async.wait_group 0;" ::: "memory");
        __syncthreads();

#pragma unroll
        for (int cc = 0; cc < 2; cc++) {
            // On the diagonal tile, warps 0-3 (rows < 64) see chunk 1 fully masked
            if (jb == qt && cc == 1 && wid < 4) continue;
            const int kb0 = cc * 64;

            // S = Q @ K^T for this 64-key chunk (8 n-tiles)
            float s[8][4];
#pragma unroll
            for (int nt = 0; nt < 8; nt++)
#pragma unroll
                for (int r = 0; r < 4; r++) s[nt][r] = 0.0f;

#pragma unroll
            for (int ks = 0; ks < 8; ks++) {
                uint32_t af[4];
                ldsm_x4(af, sQ + qOff + ks * 32u);
#pragma unroll
                for (int nt = 0; nt < 8; nt++) {
                    uint32_t bf[2];
                    ldsm_x2(bf, sK + (uint32_t)((kb0 + nt * 8)) * KPB + kOff + ks * 32u);
                    MMA_TF32(s[nt], af[0], af[1], af[2], af[3], bf[0], bf[1]);
                }
            }

            // Causal mask (diagonal tile only)
            if (jb == qt) {
                int r0g = q0 + wid * 16 + lr;
                int r1g = r0g + 8;
#pragma unroll
                for (int nt = 0; nt < 8; nt++) {
                    int c0g = j0 + kb0 + nt * 8 + lc * 2;
                    if (c0g > r0g)     s[nt][0] = -1e30f;
                    if (c0g + 1 > r0g) s[nt][1] = -1e30f;
                    if (c0g > r1g)     s[nt][2] = -1e30f;
                    if (c0g + 1 > r1g) s[nt][3] = -1e30f;
                }
            }

            // Online softmax for the chunk
            float tm0 = -1e30f, tm1 = -1e30f;
#pragma unroll
            for (int nt = 0; nt < 8; nt++) {
                tm0 = fmaxf(tm0, fmaxf(s[nt][0], s[nt][1]));
                tm1 = fmaxf(tm1, fmaxf(s[nt][2], s[nt][3]));
            }
            tm0 = fmaxf(tm0, __shfl_xor_sync(0xffffffffu, tm0, 1));
            tm0 = fmaxf(tm0, __shfl_xor_sync(0xffffffffu, tm0, 2));
            tm1 = fmaxf(tm1, __shfl_xor_sync(0xffffffffu, tm1, 1));
            tm1 = fmaxf(tm1, __shfl_xor_sync(0xffffffffu, tm1, 2));

            float mn0 = fmaxf(m0, tm0), mn1 = fmaxf(m1, tm1);
            float f0 = __expf(m0 - mn0), f1 = __expf(m1 - mn1);
            float su0 = 0.0f, su1 = 0.0f;
#pragma unroll
            for (int nt = 0; nt < 8; nt++) {
                float p0 = __expf(s[nt][0] - mn0);
                float p1 = __expf(s[nt][1] - mn0);
                float p2 = __expf(s[nt][2] - mn1);
                float p3 = __expf(s[nt][3] - mn1);
                su0 += p0 + p1;
                su1 += p2 + p3;
                s[nt][0] = __uint_as_float(f2tf32(p0));
                s[nt][1] = __uint_as_float(f2tf32(p1));
                s[nt][2] = __uint_as_float(f2tf32(p2));
                s[nt][3] = __uint_as_float(f2tf32(p3));
            }
            su0 += __shfl_xor_sync(0xffffffffu, su0, 1);
            su0 += __shfl_xor_sync(0xffffffffu, su0, 2);
            su1 += __shfl_xor_sync(0xffffffffu, su1, 1);
            su1 += __shfl_xor_sync(0xffffffffu, su1, 2);

            l0 = l0 * f0 + su0;
            l1 = l1 * f1 + su1;
            m0 = mn0; m1 = mn1;
#pragma unroll
            for (int dn = 0; dn < 8; dn++) {
                o[dn][0] *= f0; o[dn][1] *= f0;
                o[dn][2] *= f1; o[dn][3] *= f1;
            }

            // O += P @ V : shuffle-transpose S accum -> A fragments (per quad)
#pragma unroll
            for (int nt = 0; nt < 8; nt++) {
                float u0 = __shfl_sync(0xffffffffu, s[nt][0], srcA);
                float u1 = __shfl_sync(0xffffffffu, s[nt][1], srcA);
                float u2 = __shfl_sync(0xffffffffu, s[nt][2], srcA);
                float u3 = __shfl_sync(0xffffffffu, s[nt][3], srcA);
                float w0 = __shfl_sync(0xffffffffu, s[nt][0], srcB);
                float w1 = __shfl_sync(0xffffffffu, s[nt][1], srcB);
                float w2 = __shfl_sync(0xffffffffu, s[nt][2], srcB);
                float w3 = __shfl_sync(0xffffffffu, s[nt][3], srcB);
                bool odd = (lc & 1);
                uint32_t a0 = __float_as_uint(odd ? u1 : u0);
                uint32_t a1 = __float_as_uint(odd ? u3 : u2);
                uint32_t a2 = __float_as_uint(odd ? w1 : w0);
                uint32_t a3 = __float_as_uint(odd ? w3 : w2);
                const int kr = kb0 + nt * 8;
#pragma unroll
                for (int dn = 0; dn < 8; dn++) {
                    uint32_t b0 = Vs[(kr + lc) * VP + dn * 8 + lr];
                    uint32_t b1 = Vs[(kr + lc + 4) * VP + dn * 8 + lr];
                    MMA_TF32(o[dn], a0, a1, a2, a3, b0, b1);
                }
            }
        }
    }

    // Epilogue: y[B,T,C], rounded to tf32 for the final GEMM
    const int b_ = bh >> 4, h_ = bh & 15;
    const float i0 = 1.0f / l0, i1 = 1.0f / l1;
    const int r0g = q0 + wid * 16 + lr;
#pragma unroll
    for (int dn = 0; dn < 8; dn++) {
        int col = h_ * Dx + dn * 8 + lc * 2;
        float2 w0, w1;
        w0.x = __uint_as_float(f2tf32(o[dn][0] * i0));
        w0.y = __uint_as_float(f2tf32(o[dn][1] * i0));
        w1.x = __uint_as_float(f2tf32(o[dn][2] * i1));
        w1.y = __uint_as_float(f2tf32(o[dn][3] * i1));
        *(float2*)&y[((size_t)b_ * Tx + r0g) * Cx + col] = w0;
        *(float2*)&y[((size_t)b_ * Tx + r0g + 8) * Cx + col] = w1;
    }
}

// ---------------------------------------------------------------------------
extern "C" void kernel_launch(void* const* d_in, const int* in_sizes, int n_in,
                              void* d_out, int out_size)
{
    const float* x  = (const float*)d_in[0];
    // d_in[1] = att_mask (causal tril) — handled structurally in-kernel
    const float* wq = (const float*)d_in[2];
    const float* bq = (const float*)d_in[3];
    const float* wk = (const float*)d_in[4];
    const float* bk = (const float*)d_in[5];
    const float* wv = (const float*)d_in[6];
    const float* bv = (const float*)d_in[7];
    const float* wp = (const float*)d_in[8];
    const float* bp = (const float*)d_in[9];
    float* out = (float*)d_out;

    float *qp, *kp, *vp, *yp, *xr, *wr;
    cudaGetSymbolAddress((void**)&qp, g_q);
    cudaGetSymbolAddress((void**)&kp, g_k);
    cudaGetSymbolAddress((void**)&vp, g_v);
    cudaGetSymbolAddress((void**)&yp, g_y);
    cudaGetSymbolAddress((void**)&xr, g_xr);
    cudaGetSymbolAddress((void**)&wr, g_wr4);

    const int gemm_smem = 3 * 36864;   // 110592 (3 stages)
    cudaFuncSetAttribute(mma_gemm, cudaFuncAttributeMaxDynamicSharedMemorySize, gemm_smem);

    // Pre-round X + all weights to tf32 (one launch)
    round_all_kernel<<<4096 + 4 * 1024, 256>>>(x, wq, wk, wv, wp, xr, wr);

    // Fused QKV projection: grid.z selects W/bias/out
    mma_gemm<<<dim3(8, 32, 3), 256, gemm_smem>>>(
        xr, wr, wr + (size_t)Cx * Cx, wr + 2 * (size_t)Cx * Cx,
        bq, bk, bv, qp, kp, vp, 1, 1);

    const int attn_smem = 128 * (68 + 68 + 72) * 4;   // 106496
    cudaFuncSetAttribute(attn_mma, cudaFuncAttributeMaxDynamicSharedMemorySize, attn_smem);
    attn_mma<<<dim3(Tx / 128, Bx * Hx), 256, attn_smem>>>(qp, kp, vp, yp);

    // Output projection (y tf32-rounded by attn epilogue)
    mma_gemm<<<dim3(8, 32, 1), 256, gemm_smem>>>(
        yp, wr + 3 * (size_t)Cx * Cx, nullptr, nullptr,
        bp, nullptr, nullptr, out, nullptr, nullptr, 0, 0);
}

// round 15
// speedup vs baseline: 4.9319x; 1.0325x over previous
#include <cuda_runtime.h>
#include <cstdint>

// Problem constants
#define Bx 2
#define Tx 2048
#define Cx 1024
#define Hx 16
#define Dx 64
#define Mrows (Bx*Tx)   // 4096

// Scratch in __device__ globals (no allocations allowed)
__device__ float g_q[(size_t)Bx*Hx*Tx*Dx];    // [B,H,T,D] (tf32-rounded)
__device__ float g_k[(size_t)Bx*Hx*Tx*Dx];
__device__ float g_v[(size_t)Bx*Hx*Tx*Dx];
__device__ float g_y[(size_t)Mrows*Cx];       // [B*T, C]  (tf32-rounded)
__device__ float g_xr[(size_t)Mrows*Cx];      // tf32-rounded X
__device__ float g_wr4[4][(size_t)Cx*Cx];     // tf32-rounded Wq,Wk,Wv,Wp

__device__ __forceinline__ uint32_t smem_u32(const void* p) {
    uint32_t a;
    asm("{ .reg .u64 t; cvta.to.shared.u64 t, %1; cvt.u32.u64 %0, t; }" : "=r"(a) : "l"(p));
    return a;
}
__device__ __forceinline__ uint32_t f2tf32(float f) {
    uint32_t u;
    asm("cvt.rna.tf32.f32 %0, %1;" : "=r"(u) : "f"(f));
    return u;
}
__device__ __forceinline__ void ldsm_x4(uint32_t* r, uint32_t addr) {
    asm volatile("ldmatrix.sync.aligned.m8n8.x4.shared.b16 {%0,%1,%2,%3}, [%4];"
        : "=r"(r[0]), "=r"(r[1]), "=r"(r[2]), "=r"(r[3]) : "r"(addr));
}
#define MMA_TF32(C, A0,A1,A2,A3, B0,B1) \
    asm volatile("mma.sync.aligned.m16n8k8.row.col.f32.tf32.tf32.f32 " \
        "{%0,%1,%2,%3}, {%4,%5,%6,%7}, {%8,%9}, {%0,%1,%2,%3};" \
        : "+f"((C)[0]), "+f"((C)[1]), "+f"((C)[2]), "+f"((C)[3]) \
        : "r"(A0), "r"(A1), "r"(A2), "r"(A3), "r"(B0), "r"(B1))

// ---------------------------------------------------------------------------
// Fused tf32 rounding pre-pass: X (4M elems) + 4 weights (1M each).
// ---------------------------------------------------------------------------
__global__ __launch_bounds__(256) void round_all_kernel(
    const float* __restrict__ x,
    const float* __restrict__ wq, const float* __restrict__ wk,
    const float* __restrict__ wv, const float* __restrict__ wp,
    float* __restrict__ xr, float* __restrict__ wr)
{
    int bid = blockIdx.x;
    const float* src;
    float* dst;
    int off;
    if (bid < 4096) {
        src = x; dst = xr; off = bid * 1024;
    } else {
        int seg = (bid - 4096) >> 10;
        off = ((bid - 4096) & 1023) * 1024;
        src = (seg == 0) ? wq : (seg == 1) ? wk : (seg == 2) ? wv : wp;
        dst = wr + (size_t)seg * Cx * Cx;
    }
    int i = off + threadIdx.x * 4;
    float4 v = *(const float4*)(src + i);
    float4 o;
    o.x = __uint_as_float(f2tf32(v.x));
    o.y = __uint_as_float(f2tf32(v.y));
    o.z = __uint_as_float(f2tf32(v.z));
    o.w = __uint_as_float(f2tf32(v.w));
    *(float4*)(dst + i) = o;
}

// ---------------------------------------------------------------------------
// tf32 mma.sync GEMM (inputs pre-rounded; ldmatrix x4 frags for A and B;
// 1 barrier/k-iter). CTA 128x128, BK=32, 8 warps (2x4) x 64x32, 3-stage.
// grid.z selects (W, bias, out) set for fused QKV.
// ---------------------------------------------------------------------------
__global__ __launch_bounds__(256, 2) void mma_gemm(
    const float* __restrict__ X,
    const float* __restrict__ Wa, const float* __restrict__ Wb2,
    const float* __restrict__ Wc,
    const float* __restrict__ ba, const float* __restrict__ bb2,
    const float* __restrict__ bc,
    float* __restrict__ oa, float* __restrict__ ob2, float* __restrict__ oc,
    int split, int round_out)
{
    constexpr int NK = 32;
    constexpr uint32_t LDB = 144u;     // 36 floats row stride (bytes)
    constexpr uint32_t STB = 36864u;   // per stage: A 18432 + B 18432
    extern __shared__ float smf[];
    const uint32_t sb = smem_u32(smf);

    const int z = blockIdx.z;
    const float* W    = (z == 0) ? Wa : (z == 1) ? Wb2 : Wc;
    const float* bias = (z == 0) ? ba : (z == 1) ? bb2 : bc;
    float* out        = (z == 0) ? oa : (z == 1) ? ob2 : oc;

    const int tid = threadIdx.x;
    const int wid = tid >> 5, lane = tid & 31;
    const int wm = wid >> 2, wn = wid & 3;
    const int bm = blockIdx.y * 128, bn = blockIdx.x * 128;

    const float* Xb = X + (size_t)bm * 1024;
    const float* Wb = W + (size_t)bn * 1024;

    // A x4: lanes 0-15 rows, lanes 16-31 second 16B half
    const uint32_t aOff = (uint32_t)(lane & 15) * LDB + ((lane >> 4) & 1) * 16u;
    // B x4 paired: lanes 0-15 rows n..n+7 (two halves), lanes 16-31 rows n+8..n+15
    const uint32_t bOff4 = (uint32_t)(lane & 7) * LDB + ((lane >> 3) & 1) * 16u
                         + ((lane >> 4) & 1) * (8u * LDB);

    float acc[4][4][4];
#pragma unroll
    for (int mt = 0; mt < 4; mt++)
#pragma unroll
        for (int nt = 0; nt < 4; nt++)
#pragma unroll
            for (int r = 0; r < 4; r++) acc[mt][nt][r] = 0.0f;

    auto load_stage = [&](int s, int kc) {
        uint32_t A = sb + (uint32_t)s * STB;
        uint32_t B = A + 18432u;
        const float* xs = Xb + kc * 32;
        const float* ws = Wb + kc * 32;
#pragma unroll
        for (int i = 0; i < 4; i++) {
            int f = tid + i * 256;
            int r = f >> 3;
            int c4 = (f & 7) * 4;
            uint32_t off = (uint32_t)r * LDB + (uint32_t)c4 * 4u;
            asm volatile("cp.async.cg.shared.global [%0], [%1], 16;"
                         :: "r"(A + off), "l"(xs + (size_t)r * 1024 + c4) : "memory");
            asm volatile("cp.async.cg.shared.global [%0], [%1], 16;"
                         :: "r"(B + off), "l"(ws + (size_t)r * 1024 + c4) : "memory");
        }
        asm volatile("cp.async.commit_group;" ::: "memory");
    };

    load_stage(0, 0);
    load_stage(1, 1);

    for (int k = 0; k < NK; k++) {
        if (k + 1 < NK)
            asm volatile("cp.async.wait_group 1;" ::: "memory");
        else
            asm volatile("cp.async.wait_group 0;" ::: "memory");
        __syncthreads();
        // Safe: slot (k+2)%3 == (k-1)%3; its readers (iter k-1) are past this barrier.
        if (k + 2 < NK) load_stage((k + 2) % 3, k + 2);

        const uint32_t As = sb + (uint32_t)(k % 3) * STB;
        const uint32_t Bs = As + 18432u;
        const uint32_t aBase = As + (uint32_t)(wm * 64) * LDB + aOff;
        const uint32_t bBase = Bs + (uint32_t)(wn * 32) * LDB + bOff4;

#pragma unroll
        for (int kk = 0; kk < 4; kk++) {
            uint32_t af[4][4], bf[2][4];
#pragma unroll
            for (int mt = 0; mt < 4; mt++)
                ldsm_x4(af[mt], aBase + (uint32_t)(mt * 16) * LDB + kk * 32u);
#pragma unroll
            for (int np = 0; np < 2; np++)
                ldsm_x4(bf[np], bBase + (uint32_t)(np * 16) * LDB + kk * 32u);
#pragma unroll
            for (int mt = 0; mt < 4; mt++)
#pragma unroll
                for (int nt = 0; nt < 4; nt++)
                    MMA_TF32(acc[mt][nt], af[mt][0], af[mt][1], af[mt][2], af[mt][3],
                             bf[nt >> 1][(nt & 1) * 2], bf[nt >> 1][(nt & 1) * 2 + 1]);
        }
    }

    const int lr = lane >> 2, lc = lane & 3;
#pragma unroll
    for (int mt = 0; mt < 4; mt++) {
#pragma unroll
        for (int nt = 0; nt < 4; nt++) {
            int row = bm + wm * 64 + mt * 16 + lr;
            int col = bn + wn * 32 + nt * 8 + lc * 2;
            float b0 = __ldg(bias + col), b1 = __ldg(bias + col + 1);
            float2 v0 = make_float2(acc[mt][nt][0] + b0, acc[mt][nt][1] + b1);
            float2 v1 = make_float2(acc[mt][nt][2] + b0, acc[mt][nt][3] + b1);
            if (round_out) {
                v0.x = __uint_as_float(f2tf32(v0.x));
                v0.y = __uint_as_float(f2tf32(v0.y));
                v1.x = __uint_as_float(f2tf32(v1.x));
                v1.y = __uint_as_float(f2tf32(v1.y));
            }
            if (split) {
                int h_ = col >> 6, d_ = col & 63;
                int b_ = row >> 11, t_ = row & 2047;
                size_t base = (((size_t)(b_ * Hx + h_) * Tx) + t_) * Dx + d_;
                *(float2*)(out + base) = v0;
                int t2 = (row + 8) & 2047;
                size_t base2 = (((size_t)(b_ * Hx + h_) * Tx) + t2) * Dx + d_;
                *(float2*)(out + base2) = v1;
            } else {
                *(float2*)(out + (size_t)row * Cx + col) = v0;
                *(float2*)(out + (size_t)(row + 8) * Cx + col) = v1;
            }
        }
    }
}

// ---------------------------------------------------------------------------
// Tensor-core flash attention (tf32 mma.sync).
// Double-buffered K/V via cp.async: fill(jb+1) overlaps compute(jb); fill
// latency fully hidden in steady state. ldmatrix x4 Q and paired-K frags,
// shuffle-transpose P. CTA = 128 q-rows, 8 warps x 16 rows, 1 CTA/SM.
// ---------------------------------------------------------------------------
__global__ __launch_bounds__(256) void attn_mma(
    const float* __restrict__ q, const float* __restrict__ k,
    const float* __restrict__ v, float* __restrict__ y)
{
    constexpr int QP = 68, KP = 68, VP = 72;
    constexpr uint32_t QPB = QP * 4, KPB = KP * 4, VPB = VP * 4;
    constexpr uint32_t KTILE = 128u * KPB;   // 34816
    constexpr uint32_t VTILE = 128u * VPB;   // 36864
    extern __shared__ uint32_t sw[];
    uint32_t* Qs = sw;                       // 128*QP
    uint32_t* Ks = Qs + 128 * QP;            // 2 x 128*KP
    uint32_t* Vs = Ks + 2 * 128 * KP;        // 2 x 128*VP   total 178176 B

    const int bh = blockIdx.y;
    const int qt = gridDim.x - 1 - blockIdx.x;   // heaviest tiles first
    const int q0 = qt * 128;
    const int tid = threadIdx.x;
    const int wid = tid >> 5, lane = tid & 31;
    const int lr = lane >> 2, lc = lane & 3;
    const float* qb = q + (size_t)bh * Tx * Dx;
    const float* kb = k + (size_t)bh * Tx * Dx;
    const float* vb = v + (size_t)bh * Tx * Dx;

    const uint32_t sQ = smem_u32(Qs), sK0 = smem_u32(Ks), sV0 = smem_u32(Vs);
    const uint32_t qOff = (uint32_t)(lane & 15) * QPB + ((lane >> 4) & 1) * 16u
                        + (uint32_t)(wid * 16) * QPB;
    // paired-K x4: lanes 0-15 rows n..n+7 (two 16B halves), lanes 16-31 rows n+8..n+15
    const uint32_t kOff4 = (uint32_t)(lane & 7) * KPB + ((lane >> 3) & 1) * 16u
                         + ((lane >> 4) & 1) * (8u * KPB);

    auto prefetch = [&](int buf, int j0) {
        uint32_t kd = sK0 + (uint32_t)buf * KTILE;
        uint32_t vd = sV0 + (uint32_t)buf * VTILE;
#pragma unroll
        for (int l = 0; l < 8; l++) {
            int f = tid + l * 256;
            int r = f >> 4;
            uint32_t cb = (uint32_t)(f & 15) * 16u;
            const char* kg = (const char*)&kb[(size_t)(j0 + r) * Dx] + cb;
            const char* vg = (const char*)&vb[(size_t)(j0 + r) * Dx] + cb;
            asm volatile("cp.async.cg.shared.global [%0], [%1], 16;"
                         :: "r"(kd + (uint32_t)r * KPB + cb), "l"(kg) : "memory");
            asm volatile("cp.async.cg.shared.global [%0], [%1], 16;"
                         :: "r"(vd + (uint32_t)r * VPB + cb), "l"(vg) : "memory");
        }
        asm volatile("cp.async.commit_group;" ::: "memory");
    };

    // Load Q tile: raw copy with 1/8 scale folded (exact on tf32 values)
#pragma unroll
    for (int l = 0; l < 8; l++) {
        int f = tid + l * 256;
        int r = f >> 4, c4 = (f & 15) * 4;
        float4 t = *(const float4*)&qb[(size_t)(q0 + r) * Dx + c4];
        t.x *= 0.125f; t.y *= 0.125f; t.z *= 0.125f; t.w *= 0.125f;
        *(float4*)&Qs[r * QP + c4] = t;
    }
    prefetch(0, 0);

    float m0 = -1e30f, m1 = -1e30f, l0 = 0.0f, l1 = 0.0f;
    float o[8][4];
#pragma unroll
    for (int dn = 0; dn < 8; dn++)
#pragma unroll
        for (int r = 0; r < 4; r++) o[dn][r] = 0.0f;

    const uint32_t srcA = (lane & ~3) | (lc >> 1);
    const uint32_t srcB = srcA + 2;

    for (int jb = 0; jb <= qt; jb++) {
        const int j0 = jb * 128;
        const int buf = jb & 1;
        asm volatile("cp.async.wait_group 0;" ::: "memory");   // fill(jb) done
        __syncthreads();                                        // visible to all
        if (jb + 1 <= qt) prefetch(buf ^ 1, j0 + 128);          // overlaps compute

        const uint32_t sKb = sK0 + (uint32_t)buf * KTILE;
        const uint32_t* Vb = Vs + buf * 128 * VP;

#pragma unroll
        for (int cc = 0; cc < 2; cc++) {
            // On the diagonal tile, warps 0-3 (rows < 64) see chunk 1 fully masked
            if (jb == qt && cc == 1 && wid < 4) continue;
            const int kb0 = cc * 64;

            // S = Q @ K^T for this 64-key chunk (8 n-tiles, K paired x4)
            float s[8][4];
#pragma unroll
            for (int nt = 0; nt < 8; nt++)
#pragma unroll
                for (int r = 0; r < 4; r++) s[nt][r] = 0.0f;

#pragma unroll
            for (int ks = 0; ks < 8; ks++) {
                uint32_t af[4];
                ldsm_x4(af, sQ + qOff + ks * 32u);
#pragma unroll
                for (int np = 0; np < 4; np++) {
                    uint32_t bf[4];
                    ldsm_x4(bf, sKb + (uint32_t)(kb0 + np * 16) * KPB + kOff4 + ks * 32u);
                    MMA_TF32(s[np * 2],     af[0], af[1], af[2], af[3], bf[0], bf[1]);
                    MMA_TF32(s[np * 2 + 1], af[0], af[1], af[2], af[3], bf[2], bf[3]);
                }
            }

            // Causal mask (diagonal tile only)
            if (jb == qt) {
                int r0g = q0 + wid * 16 + lr;
                int r1g = r0g + 8;
#pragma unroll
                for (int nt = 0; nt < 8; nt++) {
                    int c0g = j0 + kb0 + nt * 8 + lc * 2;
                    if (c0g > r0g)     s[nt][0] = -1e30f;
                    if (c0g + 1 > r0g) s[nt][1] = -1e30f;
                    if (c0g > r1g)     s[nt][2] = -1e30f;
                    if (c0g + 1 > r1g) s[nt][3] = -1e30f;
                }
            }

            // Online softmax for the chunk
            float tm0 = -1e30f, tm1 = -1e30f;
#pragma unroll
            for (int nt = 0; nt < 8; nt++) {
                tm0 = fmaxf(tm0, fmaxf(s[nt][0], s[nt][1]));
                tm1 = fmaxf(tm1, fmaxf(s[nt][2], s[nt][3]));
            }
            tm0 = fmaxf(tm0, __shfl_xor_sync(0xffffffffu, tm0, 1));
            tm0 = fmaxf(tm0, __shfl_xor_sync(0xffffffffu, tm0, 2));
            tm1 = fmaxf(tm1, __shfl_xor_sync(0xffffffffu, tm1, 1));
            tm1 = fmaxf(tm1, __shfl_xor_sync(0xffffffffu, tm1, 2));

            float mn0 = fmaxf(m0, tm0), mn1 = fmaxf(m1, tm1);
            float f0 = __expf(m0 - mn0), f1 = __expf(m1 - mn1);
            float su0 = 0.0f, su1 = 0.0f;
#pragma unroll
            for (int nt = 0; nt < 8; nt++) {
                float p0 = __expf(s[nt][0] - mn0);
                float p1 = __expf(s[nt][1] - mn0);
                float p2 = __expf(s[nt][2] - mn1);
                float p3 = __expf(s[nt][3] - mn1);
                su0 += p0 + p1;
                su1 += p2 + p3;
                s[nt][0] = __uint_as_float(f2tf32(p0));
                s[nt][1] = __uint_as_float(f2tf32(p1));
                s[nt][2] = __uint_as_float(f2tf32(p2));
                s[nt][3] = __uint_as_float(f2tf32(p3));
            }
            su0 += __shfl_xor_sync(0xffffffffu, su0, 1);
            su0 += __shfl_xor_sync(0xffffffffu, su0, 2);
            su1 += __shfl_xor_sync(0xffffffffu, su1, 1);
            su1 += __shfl_xor_sync(0xffffffffu, su1, 2);

            l0 = l0 * f0 + su0;
            l1 = l1 * f1 + su1;
            m0 = mn0; m1 = mn1;
#pragma unroll
            for (int dn = 0; dn < 8; dn++) {
                o[dn][0] *= f0; o[dn][1] *= f0;
                o[dn][2] *= f1; o[dn][3] *= f1;
            }

            // O += P @ V : shuffle-transpose S accum -> A fragments (per quad)
#pragma unroll
            for (int nt = 0; nt < 8; nt++) {
                float u0 = __shfl_sync(0xffffffffu, s[nt][0], srcA);
                float u1 = __shfl_sync(0xffffffffu, s[nt][1], srcA);
                float u2 = __shfl_sync(0xffffffffu, s[nt][2], srcA);
                float u3 = __shfl_sync(0xffffffffu, s[nt][3], srcA);
                float w0 = __shfl_sync(0xffffffffu, s[nt][0], srcB);
                float w1 = __shfl_sync(0xffffffffu, s[nt][1], srcB);
                float w2 = __shfl_sync(0xffffffffu, s[nt][2], srcB);
                float w3 = __shfl_sync(0xffffffffu, s[nt][3], srcB);
                bool odd = (lc & 1);
                uint32_t a0 = __float_as_uint(odd ? u1 : u0);
                uint32_t a1 = __float_as_uint(odd ? u3 : u2);
                uint32_t a2 = __float_as_uint(odd ? w1 : w0);
                uint32_t a3 = __float_as_uint(odd ? w3 : w2);
                const int kr = kb0 + nt * 8;
#pragma unroll
                for (int dn = 0; dn < 8; dn++) {
                    uint32_t b0 = Vb[(kr + lc) * VP + dn * 8 + lr];
                    uint32_t b1 = Vb[(kr + lc + 4) * VP + dn * 8 + lr];
                    MMA_TF32(o[dn], a0, a1, a2, a3, b0, b1);
                }
            }
        }
    }

    // Epilogue: y[B,T,C], rounded to tf32 for the final GEMM
    const int b_ = bh >> 4, h_ = bh & 15;
    const float i0 = 1.0f / l0, i1 = 1.0f / l1;
    const int r0g = q0 + wid * 16 + lr;
#pragma unroll
    for (int dn = 0; dn < 8; dn++) {
        int col = h_ * Dx + dn * 8 + lc * 2;
        float2 w0, w1;
        w0.x = __uint_as_float(f2tf32(o[dn][0] * i0));
        w0.y = __uint_as_float(f2tf32(o[dn][1] * i0));
        w1.x = __uint_as_float(f2tf32(o[dn][2] * i1));
        w1.y = __uint_as_float(f2tf32(o[dn][3] * i1));
        *(float2*)&y[((size_t)b_ * Tx + r0g) * Cx + col] = w0;
        *(float2*)&y[((size_t)b_ * Tx + r0g + 8) * Cx + col] = w1;
    }
}

// ---------------------------------------------------------------------------
extern "C" void kernel_launch(void* const* d_in, const int* in_sizes, int n_in,
                              void* d_out, int out_size)
{
    const float* x  = (const float*)d_in[0];
    // d_in[1] = att_mask (causal tril) — handled structurally in-kernel
    const float* wq = (const float*)d_in[2];
    const float* bq = (const float*)d_in[3];
    const float* wk = (const float*)d_in[4];
    const float* bk = (const float*)d_in[5];
    const float* wv = (const float*)d_in[6];
    const float* bv = (const float*)d_in[7];
    const float* wp = (const float*)d_in[8];
    const float* bp = (const float*)d_in[9];
    float* out = (float*)d_out;

    float *qp, *kp, *vp, *yp, *xr, *wr;
    cudaGetSymbolAddress((void**)&qp, g_q);
    cudaGetSymbolAddress((void**)&kp, g_k);
    cudaGetSymbolAddress((void**)&vp, g_v);
    cudaGetSymbolAddress((void**)&yp, g_y);
    cudaGetSymbolAddress((void**)&xr, g_xr);
    cudaGetSymbolAddress((void**)&wr, g_wr4);

    const int gemm_smem = 3 * 36864;   // 110592 (3 stages)
    cudaFuncSetAttribute(mma_gemm, cudaFuncAttributeMaxDynamicSharedMemorySize, gemm_smem);

    // Pre-round X + all weights to tf32 (one launch)
    round_all_kernel<<<4096 + 4 * 1024, 256>>>(x, wq, wk, wv, wp, xr, wr);

    // Fused QKV projection: grid.z selects W/bias/out
    mma_gemm<<<dim3(8, 32, 3), 256, gemm_smem>>>(
        xr, wr, wr + (size_t)Cx * Cx, wr + 2 * (size_t)Cx * Cx,
        bq, bk, bv, qp, kp, vp, 1, 1);

    // attn smem: Q 34816 + 2*K 69632 + 2*V 73728 = 178176
    const int attn_smem = 128 * 68 * 4 + 2 * 128 * 68 * 4 + 2 * 128 * 72 * 4;
    cudaFuncSetAttribute(attn_mma, cudaFuncAttributeMaxDynamicSharedMemorySize, attn_smem);
    attn_mma<<<dim3(Tx / 128, Bx * Hx), 256, attn_smem>>>(qp, kp, vp, yp);

    // Output projection (y tf32-rounded by attn epilogue)
    mma_gemm<<<dim3(8, 32, 1), 256, gemm_smem>>>(
        yp, wr + 3 * (size_t)Cx * Cx, nullptr, nullptr,
        bp, nullptr, nullptr, out, nullptr, nullptr, 0, 0);
}